// round 8
// baseline (speedup 1.0000x reference)
#include <cuda_runtime.h>
#include <stdint.h>

#define B_ 8
#define L_ 1024
#define D_ 768
#define H_ 12

// ---------------- scratch (device globals; no allocations allowed) ----------
__device__ float g_q[B_ * L_ * D_];
__device__ float g_k[B_ * L_ * D_];
__device__ float g_v[B_ * L_ * D_];
__device__ float g_n[B_ * L_ * D_];
__device__ float g_nkT[B_ * D_ * L_];
__device__ float g_G[B_ * D_ * D_];
__device__ float g_T[B_ * L_ * D_];
__device__ float g_enh[(long)B_ * L_ * L_];
__device__ float g_att[B_ * L_ * D_];

// ---------------- helpers ----------------------------------------------------
__device__ __forceinline__ uint32_t smem_u32(const void* p) {
    uint32_t a;
    asm("{ .reg .u64 t; cvta.to.shared.u64 t, %1; cvt.u32.u64 %0, t; }"
        : "=r"(a) : "l"(p));
    return a;
}
__device__ __forceinline__ uint32_t f2tf32(float x) {
    uint32_t r;
    asm("cvt.rna.tf32.f32 %0, %1;" : "=r"(r) : "f"(x));
    return r;
}
__device__ __forceinline__ void split4(float4 a, uint4& h, uint4& l) {
    h.x = f2tf32(a.x); l.x = f2tf32(a.x - __uint_as_float(h.x));
    h.y = f2tf32(a.y); l.y = f2tf32(a.y - __uint_as_float(h.y));
    h.z = f2tf32(a.z); l.z = f2tf32(a.z - __uint_as_float(h.z));
    h.w = f2tf32(a.w); l.w = f2tf32(a.w - __uint_as_float(h.w));
}
__device__ __forceinline__ uint4 hi4(float4 a) {
    uint4 h;
    h.x = f2tf32(a.x); h.y = f2tf32(a.y);
    h.z = f2tf32(a.z); h.w = f2tf32(a.w);
    return h;
}
__device__ __forceinline__ void ldsm4(uint32_t* r, uint32_t addr) {
    asm volatile("ldmatrix.sync.aligned.m8n8.x4.shared.b16 {%0,%1,%2,%3}, [%4];"
                 : "=r"(r[0]), "=r"(r[1]), "=r"(r[2]), "=r"(r[3]) : "r"(addr));
}
__device__ __forceinline__ void mma8(float* d, const uint32_t* a, const uint32_t* b) {
    asm volatile(
        "mma.sync.aligned.m16n8k8.row.col.f32.tf32.tf32.f32 "
        "{%0,%1,%2,%3}, {%4,%5,%6,%7}, {%8,%9}, {%0,%1,%2,%3};"
        : "+f"(d[0]), "+f"(d[1]), "+f"(d[2]), "+f"(d[3])
        : "r"(a[0]), "r"(a[1]), "r"(a[2]), "r"(a[3]), "r"(b[0]), "r"(b[1]));
}

// ---------------------------------------------------------------------------
// GEMM core: CTA tile 128x64, K-chunk 32, 8 warps (2m x 4n), warp tile 64x16.
// 2-stage double buffer.
// Stage layout (floats, rows padded to 36):
//   TERMS==3: Ah[128*36] Al[128*36] Bh[64*36] Bl[64*36]  (13824 fl, 55.3KB)
//   TERMS==2: Ah[128*36]            Bh[64*36] Bl[64*36]  ( 9216 fl, 36.9KB)
// TERMS==3 accuracy ~fp32 (use on the enh amplification chain: q,k,nk,G,T,enh).
// TERMS==2 ~tf32-rounding-on-A (safe only on non-amplified paths: v, out).
// ---------------------------------------------------------------------------
#define A_FL 4608   // 128*36
#define B_FL 2304   // 64*36

template <int TERMS>
__device__ __forceinline__ void gemm_core(
    const float* __restrict__ A, const float* __restrict__ B,
    float* __restrict__ C, const float* __restrict__ bias,
    int N, int K, float* sm)
{
    constexpr int AH = 0;
    constexpr int AL = A_FL;                              // 3-term only
    constexpr int BH = (TERMS == 3) ? 2 * A_FL : A_FL;
    constexpr int BL = BH + B_FL;
    constexpr int STGF = BL + B_FL;
    const uint32_t smb = smem_u32(sm);

    const int tid = threadIdx.x;
    const int lane = tid & 31;
    const int warp = tid >> 5;
    const int wm = warp >> 2;        // 0..1 -> 64-row half
    const int wn = warp & 3;         // 0..3 -> 16-col slice
    const int bm = blockIdx.y * 128;
    const int bn = blockIdx.x * 64;

    const int row0 = tid >> 3;       // 0..31
    const int c4 = (tid & 7) << 2;   // 0..28
    const float* Ap = A + (long)(bm + row0) * K + c4;
    const float* Bp = B + (long)(bn + row0) * K + c4;  // rows row0, row0+32

    const uint32_t aOff =
        ((((uint32_t)(wm * 64 + (lane & 15)) * 36u) + ((lane & 16) >> 2)) << 2);
    const uint32_t bOff =
        ((((uint32_t)(wn * 16 + (lane & 7) + ((lane & 16) >> 1)) * 36u) +
          ((lane & 8) >> 1)) << 2) + (uint32_t)(BH << 2);

    float acc[4][2][4];
#pragma unroll
    for (int m = 0; m < 4; m++)
#pragma unroll
        for (int n = 0; n < 2; n++)
#pragma unroll
            for (int r = 0; r < 4; r++) acc[m][n][r] = 0.f;

    const int NC = K >> 5;

    // prologue: chunk 0 -> stage 0
    {
        float4 av[4], bv[2];
#pragma unroll
        for (int it = 0; it < 4; it++)
            av[it] = *(const float4*)(Ap + (long)(it * 32) * K);
#pragma unroll
        for (int it = 0; it < 2; it++)
            bv[it] = *(const float4*)(Bp + (long)(it * 32) * K);
#pragma unroll
        for (int it = 0; it < 4; it++) {
            const int idx = (row0 + it * 32) * 36 + c4;
            uint4 h, l;
            split4(av[it], h, l);
            *(uint4*)(sm + AH + idx) = h;
            if (TERMS == 3) *(uint4*)(sm + AL + idx) = l;
        }
#pragma unroll
        for (int it = 0; it < 2; it++) {
            const int idx = (row0 + it * 32) * 36 + c4;
            uint4 h, l;
            split4(bv[it], h, l);
            *(uint4*)(sm + BH + idx) = h;
            *(uint4*)(sm + BL + idx) = l;
        }
    }
    __syncthreads();

    for (int c = 0; c < NC; c++) {
        const int buf = c & 1;
        float4 av[4], bv[2];
        if (c + 1 < NC) {
            const int k0 = (c + 1) << 5;
#pragma unroll
            for (int it = 0; it < 4; it++)
                av[it] = *(const float4*)(Ap + (long)(it * 32) * K + k0);
#pragma unroll
            for (int it = 0; it < 2; it++)
                bv[it] = *(const float4*)(Bp + (long)(it * 32) * K + k0);
        }

        const uint32_t stB = smb + (uint32_t)buf * (STGF << 2);
        const uint32_t aH = stB + aOff;
        const uint32_t bHa = stB + bOff;
        const uint32_t bLa = bHa + (uint32_t)(B_FL << 2);
#pragma unroll
        for (int s = 0; s < 4; s++) {
            const uint32_t ks = (uint32_t)s * 32;
            uint32_t bh[4], bl[4];
            ldsm4(bh, bHa + ks);
            ldsm4(bl, bLa + ks);
            uint32_t af[16];
#pragma unroll
            for (int m = 0; m < 4; m++)
                ldsm4(af + 4 * m, aH + ks + ((uint32_t)(m * 16 * 36) << 2));
#pragma unroll
            for (int m = 0; m < 4; m++)
#pragma unroll
                for (int n = 0; n < 2; n++) {
                    mma8(acc[m][n], af + 4 * m, bh + 2 * n);
                    mma8(acc[m][n], af + 4 * m, bl + 2 * n);
                }
            if (TERMS == 3) {
                const uint32_t aLa = aH + (uint32_t)(A_FL << 2);
#pragma unroll
                for (int m = 0; m < 4; m++)
                    ldsm4(af + 4 * m, aLa + ks + ((uint32_t)(m * 16 * 36) << 2));
#pragma unroll
                for (int m = 0; m < 4; m++)
#pragma unroll
                    for (int n = 0; n < 2; n++)
                        mma8(acc[m][n], af + 4 * m, bh + 2 * n);
            }
        }

        if (c + 1 < NC) {
            float* st = sm + (buf ^ 1) * STGF;
#pragma unroll
            for (int it = 0; it < 4; it++) {
                const int idx = (row0 + it * 32) * 36 + c4;
                uint4 h, l;
                split4(av[it], h, l);
                *(uint4*)(st + AH + idx) = h;
                if (TERMS == 3) *(uint4*)(st + AL + idx) = l;
            }
#pragma unroll
            for (int it = 0; it < 2; it++) {
                const int idx = (row0 + it * 32) * 36 + c4;
                uint4 h, l;
                split4(bv[it], h, l);
                *(uint4*)(st + BH + idx) = h;
                *(uint4*)(st + BL + idx) = l;
            }
        }
        __syncthreads();
    }

    const int g = lane >> 2;
    const int t = lane & 3;
#pragma unroll
    for (int n = 0; n < 2; n++) {
        const int col = bn + wn * 16 + n * 8 + t * 2;
        float b0 = 0.f, b1 = 0.f;
        if (bias) { b0 = bias[col]; b1 = bias[col + 1]; }
#pragma unroll
        for (int m = 0; m < 4; m++) {
            const int r0 = bm + wm * 64 + m * 16 + g;
            float2 v0 = make_float2(acc[m][n][0] + b0, acc[m][n][1] + b1);
            float2 v1 = make_float2(acc[m][n][2] + b0, acc[m][n][3] + b1);
            *(float2*)(C + (long)r0 * N + col) = v0;
            *(float2*)(C + (long)(r0 + 8) * N + col) = v1;
        }
    }
}

template <int TERMS>
__global__ void __launch_bounds__(256, 2) tc_gemm(
    const float* __restrict__ A, const float* __restrict__ B,
    float* __restrict__ C, const float* __restrict__ bias,
    int N, int K, long sA, long sB, long sC)
{
    extern __shared__ float sm[];
    gemm_core<TERMS>(A + (long)blockIdx.z * sA, B + (long)blockIdx.z * sB,
                     C + (long)blockIdx.z * sC, bias, N, K, sm);
}

// Merged projections: z selects (input, W, bias, output); z==3 (v) is 2-term.
struct ProjArgs {
    const float* in[4];
    const float* W[4];
    const float* bias[4];
    float* out[4];
};

__global__ void __launch_bounds__(256, 2) tc_proj(ProjArgs p)
{
    extern __shared__ float sm[];
    const int z = blockIdx.z;
    if (z != 3)
        gemm_core<3>(p.in[z], p.W[z], p.out[z], p.bias[z], D_, D_, sm);
    else
        gemm_core<2>(p.in[z], p.W[z], p.out[z], p.bias[z], D_, D_, sm);
}

// ---------------------------------------------------------------------------
// Batched transpose: in [B][L][D] -> out [B][D][L]
// ---------------------------------------------------------------------------
__global__ void transpose_ld(const float* __restrict__ in, float* __restrict__ out)
{
    __shared__ float t[32][33];
    const int b = blockIdx.z;
    const int d0 = blockIdx.x * 32;
    const int l0 = blockIdx.y * 32;
    const int x = threadIdx.x;
    const int y = threadIdx.y;
    const float* ib = in + ((long)b * L_ + l0) * D_ + d0;
#pragma unroll
    for (int i = y; i < 32; i += 8) t[i][x] = ib[(long)i * D_ + x];
    __syncthreads();
    float* ob = out + ((long)b * D_ + d0) * L_ + l0;
#pragma unroll
    for (int i = y; i < 32; i += 8) ob[(long)i * L_ + x] = t[x][i];
}

// ---------------------------------------------------------------------------
// Fused attention via mma.sync (validated in R6).
// ---------------------------------------------------------------------------
__global__ void __launch_bounds__(256, 2) attn_mma(
    const float* __restrict__ Q, const float* __restrict__ K,
    const float* __restrict__ V, const float* __restrict__ E,
    float* __restrict__ O)
{
    extern __shared__ float sh[];
    float* sQ = sh;                    // 128*68
    float* sK = sh + 128 * 68;         // 64*68
    float* sVh = sK + 64 * 68;         // [d][key]

    const int b = blockIdx.y / H_;
    const int h = blockIdx.y % H_;
    const int l0 = blockIdx.x * 128;
    const int tid = threadIdx.x;
    const int lane = tid & 31;
    const int w = tid >> 5;
    const int g = lane >> 2;
    const int t = lane & 3;

    const float* qb = Q + ((long)b * L_ + l0) * D_ + h * 64;
    const float* kb = K + (long)b * L_ * D_ + h * 64;
    const float* vb = V + (long)b * L_ * D_ + h * 64;
    const float* e0 = E + ((long)b * L_ + l0 + w * 16 + g) * L_;
    const float* e1 = e0 + 8 * L_;

#pragma unroll
    for (int it = 0; it < 8; it++) {
        int f = tid + it * 256;
        int row = f >> 4;
        int d4 = (f & 15) << 2;
        float4 v = *(const float4*)(qb + (long)row * D_ + d4);
        *(uint4*)(sQ + row * 68 + d4) = hi4(v);
    }

    const uint32_t sQa = smem_u32(sQ) +
        ((((uint32_t)(w * 16 + (lane & 15)) * 68u) + ((lane & 16) >> 2)) << 2);
    const uint32_t bPat =
        ((((uint32_t)((lane & 7) + ((lane & 16) >> 1)) * 68u) +
          ((lane & 8) >> 1)) << 2);
    const uint32_t sKa = smem_u32(sK) + bPat;
    const uint32_t sVha = smem_u32(sVh) + bPat;
    const uint32_t R16 = (16 * 68) << 2;

    float o[8][4];
#pragma unroll
    for (int j = 0; j < 8; j++)
#pragma unroll
        for (int r = 0; r < 4; r++) o[j][r] = 0.f;
    float m0 = -1e30f, m1 = -1e30f, sum0 = 0.f, sum1 = 0.f;

    for (int jb = 0; jb < 16; jb++) {
        __syncthreads();
#pragma unroll
        for (int it = 0; it < 4; it++) {
            int f = tid + it * 256;
            int key = f >> 4;
            int d4 = (f & 15) << 2;
            float4 v = *(const float4*)(kb + (long)(jb * 64 + key) * D_ + d4);
            *(uint4*)(sK + key * 68 + d4) = hi4(v);
        }
#pragma unroll
        for (int it = 0; it < 4; it++) {
            int f = tid + it * 256;
            int key = f >> 4;
            int d4 = (f & 15) << 2;
            float4 v = *(const float4*)(vb + (long)(jb * 64 + key) * D_ + d4);
            float vv[4] = {v.x, v.y, v.z, v.w};
#pragma unroll
            for (int i = 0; i < 4; i++)
                *(uint32_t*)(sVh + (d4 + i) * 68 + key) = f2tf32(vv[i]);
        }
        __syncthreads();

        float accS[8][4];
#pragma unroll
        for (int j = 0; j < 8; j++)
#pragma unroll
            for (int r = 0; r < 4; r++) accS[j][r] = 0.f;
#pragma unroll
        for (int s = 0; s < 8; s++) {
            const uint32_t ks = (uint32_t)s * 32;
            uint32_t af[4], bf[16];
            ldsm4(af, sQa + ks);
            ldsm4(bf + 0,  sKa + ks);
            ldsm4(bf + 4,  sKa + ks + R16);
            ldsm4(bf + 8,  sKa + ks + 2 * R16);
            ldsm4(bf + 12, sKa + ks + 3 * R16);
#pragma unroll
            for (int j = 0; j < 8; j++) mma8(accS[j], af, bf + 2 * j);
        }

#pragma unroll
        for (int j = 0; j < 8; j++) {
            const int col = jb * 64 + 8 * j + 2 * t;
            float2 ea = *(const float2*)(e0 + col);
            float2 ebv = *(const float2*)(e1 + col);
            accS[j][0] = (accS[j][0] + ea.x) * 0.0625f;
            accS[j][1] = (accS[j][1] + ea.y) * 0.0625f;
            accS[j][2] = (accS[j][2] + ebv.x) * 0.0625f;
            accS[j][3] = (accS[j][3] + ebv.y) * 0.0625f;
        }

        float mx0 = -1e30f, mx1 = -1e30f;
#pragma unroll
        for (int j = 0; j < 8; j++) {
            mx0 = fmaxf(mx0, fmaxf(accS[j][0], accS[j][1]));
            mx1 = fmaxf(mx1, fmaxf(accS[j][2], accS[j][3]));
        }
#pragma unroll
        for (int off = 1; off <= 2; off <<= 1) {
            mx0 = fmaxf(mx0, __shfl_xor_sync(0xffffffffu, mx0, off));
            mx1 = fmaxf(mx1, __shfl_xor_sync(0xffffffffu, mx1, off));
        }
        const float nm0 = fmaxf(m0, mx0), nm1 = fmaxf(m1, mx1);
        const float sc0 = __expf(m0 - nm0), sc1 = __expf(m1 - nm1);
        float rs0 = 0.f, rs1 = 0.f;
#pragma unroll
        for (int j = 0; j < 8; j++) {
            accS[j][0] = __expf(accS[j][0] - nm0);
            accS[j][1] = __expf(accS[j][1] - nm0);
            accS[j][2] = __expf(accS[j][2] - nm1);
            accS[j][3] = __expf(accS[j][3] - nm1);
            rs0 += accS[j][0] + accS[j][1];
            rs1 += accS[j][2] + accS[j][3];
        }
#pragma unroll
        for (int off = 1; off <= 2; off <<= 1) {
            rs0 += __shfl_xor_sync(0xffffffffu, rs0, off);
            rs1 += __shfl_xor_sync(0xffffffffu, rs1, off);
        }
        sum0 = sum0 * sc0 + rs0;
        sum1 = sum1 * sc1 + rs1;
        m0 = nm0; m1 = nm1;
#pragma unroll
        for (int j = 0; j < 8; j++) {
            o[j][0] *= sc0; o[j][1] *= sc0;
            o[j][2] *= sc1; o[j][3] *= sc1;
        }

        const int sl0 = (lane & ~3) | (t >> 1);
        const int sl2 = sl0 + 2;
#pragma unroll
        for (int kt = 0; kt < 8; kt++) {
            float p00 = __shfl_sync(0xffffffffu, accS[kt][0], sl0);
            float p01 = __shfl_sync(0xffffffffu, accS[kt][1], sl0);
            float p20 = __shfl_sync(0xffffffffu, accS[kt][0], sl2);
            float p21 = __shfl_sync(0xffffffffu, accS[kt][1], sl2);
            float p10 = __shfl_sync(0xffffffffu, accS[kt][2], sl0);
            float p11 = __shfl_sync(0xffffffffu, accS[kt][3], sl0);
            float p30 = __shfl_sync(0xffffffffu, accS[kt][2], sl2);
            float p31 = __shfl_sync(0xffffffffu, accS[kt][3], sl2);
            float a0 = (t & 1) ? p01 : p00;
            float a1 = (t & 1) ? p11 : p10;
            float a2 = (t & 1) ? p21 : p20;
            float a3 = (t & 1) ? p31 : p30;
            uint32_t ah[4];
            ah[0] = f2tf32(a0); ah[1] = f2tf32(a1);
            ah[2] = f2tf32(a2); ah[3] = f2tf32(a3);

            const uint32_t ks = (uint32_t)kt * 32;
            uint32_t bvr[16];
            ldsm4(bvr + 0,  sVha + ks);
            ldsm4(bvr + 4,  sVha + ks + R16);
            ldsm4(bvr + 8,  sVha + ks + 2 * R16);
            ldsm4(bvr + 12, sVha + ks + 3 * R16);
#pragma unroll
            for (int j = 0; j < 8; j++)
                mma8(o[j], ah, bvr + 2 * j);
        }
    }

    const float inv0 = 1.f / sum0, inv1 = 1.f / sum1;
    float* ob = O + ((long)b * L_ + l0 + w * 16) * D_ + h * 64;
#pragma unroll
    for (int j = 0; j < 8; j++) {
        const int col = 8 * j + 2 * t;
        *(float2*)(ob + (long)g * D_ + col) =
            make_float2(o[j][0] * inv0, o[j][1] * inv0);
        *(float2*)(ob + (long)(g + 8) * D_ + col) =
            make_float2(o[j][2] * inv1, o[j][3] * inv1);
    }
}

// ---------------------------------------------------------------------------
extern "C" void kernel_launch(void* const* d_in, const int* in_sizes, int n_in,
                              void* d_out, int out_size)
{
    const float* query = (const float*)d_in[0];
    const float* key   = (const float*)d_in[1];
    const float* value = (const float*)d_in[2];
    const float* news  = (const float*)d_in[3];
    const float* Wq = (const float*)d_in[4];
    const float* bq = (const float*)d_in[5];
    const float* Wk = (const float*)d_in[6];
    const float* bk = (const float*)d_in[7];
    const float* Wv = (const float*)d_in[8];
    const float* bv = (const float*)d_in[9];
    const float* Wn = (const float*)d_in[10];
    const float* bn = (const float*)d_in[11];
    const float* Wo = (const float*)d_in[12];
    const float* bo = (const float*)d_in[13];
    // d_in[14] = pos. Mathematically irrelevant (swapaxes of swapped enh == enh).

    float *pq, *pk, *pv, *pn, *pnkT, *pG, *pT, *penh, *patt;
    cudaGetSymbolAddress((void**)&pq,   g_q);
    cudaGetSymbolAddress((void**)&pk,   g_k);
    cudaGetSymbolAddress((void**)&pv,   g_v);
    cudaGetSymbolAddress((void**)&pn,   g_n);
    cudaGetSymbolAddress((void**)&pnkT, g_nkT);
    cudaGetSymbolAddress((void**)&pG,   g_G);
    cudaGetSymbolAddress((void**)&pT,   g_T);
    cudaGetSymbolAddress((void**)&penh, g_enh);
    cudaGetSymbolAddress((void**)&patt, g_att);

    const int M = B_ * L_;  // 8192
    dim3 blk(256);
    const int smem3 = 2 * (2 * A_FL + 2 * B_FL) * 4;  // 110592
    const int smem2 = 2 * (A_FL + 2 * B_FL) * 4;      // 73728
    cudaFuncSetAttribute(tc_proj,    cudaFuncAttributeMaxDynamicSharedMemorySize, smem3);
    cudaFuncSetAttribute(tc_gemm<3>, cudaFuncAttributeMaxDynamicSharedMemorySize, smem3);
    cudaFuncSetAttribute(tc_gemm<2>, cudaFuncAttributeMaxDynamicSharedMemorySize, smem2);

    // all 4 projections in one launch (z: 0=q, 1=k, 2=nk 3-term; 3=v 2-term)
    ProjArgs pa;
    pa.in[0] = query; pa.in[1] = key; pa.in[2] = news; pa.in[3] = value;
    pa.W[0] = Wq; pa.W[1] = Wk; pa.W[2] = Wn; pa.W[3] = Wv;
    pa.bias[0] = bq; pa.bias[1] = bk; pa.bias[2] = bn; pa.bias[3] = bv;
    pa.out[0] = pq; pa.out[1] = pk; pa.out[2] = pn; pa.out[3] = pv;
    tc_proj<<<dim3(D_ / 64, M / 128, 4), blk, smem3>>>(pa);

    // enh = q (nk^T nk) k^T, restructured (3-term: chain amplifies rounding!)
    transpose_ld<<<dim3(D_ / 32, L_ / 32, B_), dim3(32, 8)>>>(pn, pnkT);
    tc_gemm<3><<<dim3(D_ / 64, D_ / 128, B_), blk, smem3>>>(pnkT, pnkT, pG, nullptr,
        D_, L_, (long)D_ * L_, (long)D_ * L_, (long)D_ * D_);
    tc_gemm<3><<<dim3(D_ / 64, L_ / 128, B_), blk, smem3>>>(pq, pG, pT, nullptr,
        D_, D_, (long)L_ * D_, (long)D_ * D_, (long)L_ * D_);
    tc_gemm<3><<<dim3(L_ / 64, L_ / 128, B_), blk, smem3>>>(pT, pk, penh, nullptr,
        L_, D_, (long)L_ * D_, (long)L_ * D_, (long)L_ * L_);

    // fused attention
    const int attn_smem = (128 * 68 + 2 * 64 * 68) * 4;  // 69632
    cudaFuncSetAttribute(attn_mma, cudaFuncAttributeMaxDynamicSharedMemorySize,
                         attn_smem);
    attn_mma<<<dim3(L_ / 128, B_ * H_), blk, attn_smem>>>(pq, pk, pv, penh, patt);

    // output projection (2-term) -> d_out
    tc_gemm<2><<<dim3(D_ / 64, M / 128, 1), blk, smem2>>>(patt, Wo, (float*)d_out, bo,
                                                          D_, D_, 0, 0, 0);
}

// round 9
// speedup vs baseline: 1.1340x; 1.1340x over previous
#include <cuda_runtime.h>
#include <cuda_bf16.h>
#include <stdint.h>

#define B_ 8
#define L_ 1024
#define D_ 768
#define H_ 12

// ---------------- scratch (device globals; no allocations allowed) ----------
__device__ float g_q[B_ * L_ * D_];
__device__ float g_k[B_ * L_ * D_];
__device__ float g_v[B_ * L_ * D_];
__device__ float g_n[B_ * L_ * D_];
__device__ float g_nkT[B_ * D_ * L_];
__device__ float g_G[B_ * D_ * D_];
__device__ float g_T[B_ * L_ * D_];
__device__ float g_enh[(long)B_ * L_ * L_];
__device__ float g_att[B_ * L_ * D_];

// ---------------- helpers ----------------------------------------------------
__device__ __forceinline__ uint32_t smem_u32(const void* p) {
    uint32_t a;
    asm("{ .reg .u64 t; cvta.to.shared.u64 t, %1; cvt.u32.u64 %0, t; }"
        : "=r"(a) : "l"(p));
    return a;
}
__device__ __forceinline__ uint32_t f2tf32(float x) {
    uint32_t r;
    asm("cvt.rna.tf32.f32 %0, %1;" : "=r"(r) : "f"(x));
    return r;
}
__device__ __forceinline__ void split4(float4 a, uint4& h, uint4& l) {
    h.x = f2tf32(a.x); l.x = f2tf32(a.x - __uint_as_float(h.x));
    h.y = f2tf32(a.y); l.y = f2tf32(a.y - __uint_as_float(h.y));
    h.z = f2tf32(a.z); l.z = f2tf32(a.z - __uint_as_float(h.z));
    h.w = f2tf32(a.w); l.w = f2tf32(a.w - __uint_as_float(h.w));
}
__device__ __forceinline__ uint4 hi4(float4 a) {
    uint4 h;
    h.x = f2tf32(a.x); h.y = f2tf32(a.y);
    h.z = f2tf32(a.z); h.w = f2tf32(a.w);
    return h;
}
__device__ __forceinline__ void ldsm4(uint32_t* r, uint32_t addr) {
    asm volatile("ldmatrix.sync.aligned.m8n8.x4.shared.b16 {%0,%1,%2,%3}, [%4];"
                 : "=r"(r[0]), "=r"(r[1]), "=r"(r[2]), "=r"(r[3]) : "r"(addr));
}
__device__ __forceinline__ void mma8(float* d, const uint32_t* a, const uint32_t* b) {
    asm volatile(
        "mma.sync.aligned.m16n8k8.row.col.f32.tf32.tf32.f32 "
        "{%0,%1,%2,%3}, {%4,%5,%6,%7}, {%8,%9}, {%0,%1,%2,%3};"
        : "+f"(d[0]), "+f"(d[1]), "+f"(d[2]), "+f"(d[3])
        : "r"(a[0]), "r"(a[1]), "r"(a[2]), "r"(a[3]), "r"(b[0]), "r"(b[1]));
}
__device__ __forceinline__ void mma16(float* d, const uint32_t* a, const uint32_t* b) {
    asm volatile(
        "mma.sync.aligned.m16n8k16.row.col.f32.bf16.bf16.f32 "
        "{%0,%1,%2,%3}, {%4,%5,%6,%7}, {%8,%9}, {%0,%1,%2,%3};"
        : "+f"(d[0]), "+f"(d[1]), "+f"(d[2]), "+f"(d[3])
        : "r"(a[0]), "r"(a[1]), "r"(a[2]), "r"(a[3]), "r"(b[0]), "r"(b[1]));
}
// bf16 2-level split of 4 floats -> hi(4xbf16 as uint2), lo(uint2)
__device__ __forceinline__ void splitbf4(float4 a, uint2& h, uint2& l) {
    float e[4] = {a.x, a.y, a.z, a.w};
    uint16_t hh[4], ll[4];
#pragma unroll
    for (int i = 0; i < 4; i++) {
        __nv_bfloat16 bh = __float2bfloat16_rn(e[i]);
        float hf = __bfloat162float(bh);
        __nv_bfloat16 bl = __float2bfloat16_rn(e[i] - hf);
        hh[i] = *reinterpret_cast<uint16_t*>(&bh);
        ll[i] = *reinterpret_cast<uint16_t*>(&bl);
    }
    h.x = (uint32_t)hh[0] | ((uint32_t)hh[1] << 16);
    h.y = (uint32_t)hh[2] | ((uint32_t)hh[3] << 16);
    l.x = (uint32_t)ll[0] | ((uint32_t)ll[1] << 16);
    l.y = (uint32_t)ll[2] | ((uint32_t)ll[3] << 16);
}

// ---------------------------------------------------------------------------
// tf32 GEMM core: CTA 128x64, K-chunk 32, 8 warps (2m x 4n), warp tile 64x16.
// TERMS==3 ~fp32 accuracy; TERMS==2 ~tf32-rounding-on-A (non-amplified only).
// ---------------------------------------------------------------------------
#define A_FL 4608   // 128*36
#define B_FL 2304   // 64*36

template <int TERMS>
__device__ __forceinline__ void gemm_core(
    const float* __restrict__ A, const float* __restrict__ B,
    float* __restrict__ C, const float* __restrict__ bias,
    int N, int K, float* sm)
{
    constexpr int AH = 0;
    constexpr int AL = A_FL;
    constexpr int BH = (TERMS == 3) ? 2 * A_FL : A_FL;
    constexpr int BL = BH + B_FL;
    constexpr int STGF = BL + B_FL;
    const uint32_t smb = smem_u32(sm);

    const int tid = threadIdx.x;
    const int lane = tid & 31;
    const int warp = tid >> 5;
    const int wm = warp >> 2;
    const int wn = warp & 3;
    const int bm = blockIdx.y * 128;
    const int bn = blockIdx.x * 64;

    const int row0 = tid >> 3;
    const int c4 = (tid & 7) << 2;
    const float* Ap = A + (long)(bm + row0) * K + c4;
    const float* Bp = B + (long)(bn + row0) * K + c4;

    const uint32_t aOff =
        ((((uint32_t)(wm * 64 + (lane & 15)) * 36u) + ((lane & 16) >> 2)) << 2);
    const uint32_t bOff =
        ((((uint32_t)(wn * 16 + (lane & 7) + ((lane & 16) >> 1)) * 36u) +
          ((lane & 8) >> 1)) << 2) + (uint32_t)(BH << 2);

    float acc[4][2][4];
#pragma unroll
    for (int m = 0; m < 4; m++)
#pragma unroll
        for (int n = 0; n < 2; n++)
#pragma unroll
            for (int r = 0; r < 4; r++) acc[m][n][r] = 0.f;

    const int NC = K >> 5;

    {
        float4 av[4], bv[2];
#pragma unroll
        for (int it = 0; it < 4; it++)
            av[it] = *(const float4*)(Ap + (long)(it * 32) * K);
#pragma unroll
        for (int it = 0; it < 2; it++)
            bv[it] = *(const float4*)(Bp + (long)(it * 32) * K);
#pragma unroll
        for (int it = 0; it < 4; it++) {
            const int idx = (row0 + it * 32) * 36 + c4;
            uint4 h, l;
            split4(av[it], h, l);
            *(uint4*)(sm + AH + idx) = h;
            if (TERMS == 3) *(uint4*)(sm + AL + idx) = l;
        }
#pragma unroll
        for (int it = 0; it < 2; it++) {
            const int idx = (row0 + it * 32) * 36 + c4;
            uint4 h, l;
            split4(bv[it], h, l);
            *(uint4*)(sm + BH + idx) = h;
            *(uint4*)(sm + BL + idx) = l;
        }
    }
    __syncthreads();

    for (int c = 0; c < NC; c++) {
        const int buf = c & 1;
        float4 av[4], bv[2];
        if (c + 1 < NC) {
            const int k0 = (c + 1) << 5;
#pragma unroll
            for (int it = 0; it < 4; it++)
                av[it] = *(const float4*)(Ap + (long)(it * 32) * K + k0);
#pragma unroll
            for (int it = 0; it < 2; it++)
                bv[it] = *(const float4*)(Bp + (long)(it * 32) * K + k0);
        }

        const uint32_t stB = smb + (uint32_t)buf * (STGF << 2);
        const uint32_t aH = stB + aOff;
        const uint32_t bHa = stB + bOff;
        const uint32_t bLa = bHa + (uint32_t)(B_FL << 2);
#pragma unroll
        for (int s = 0; s < 4; s++) {
            const uint32_t ks = (uint32_t)s * 32;
            uint32_t bh[4], bl[4];
            ldsm4(bh, bHa + ks);
            ldsm4(bl, bLa + ks);
            uint32_t af[16];
#pragma unroll
            for (int m = 0; m < 4; m++)
                ldsm4(af + 4 * m, aH + ks + ((uint32_t)(m * 16 * 36) << 2));
#pragma unroll
            for (int m = 0; m < 4; m++)
#pragma unroll
                for (int n = 0; n < 2; n++) {
                    mma8(acc[m][n], af + 4 * m, bh + 2 * n);
                    mma8(acc[m][n], af + 4 * m, bl + 2 * n);
                }
            if (TERMS == 3) {
                const uint32_t aLa = aH + (uint32_t)(A_FL << 2);
#pragma unroll
                for (int m = 0; m < 4; m++)
                    ldsm4(af + 4 * m, aLa + ks + ((uint32_t)(m * 16 * 36) << 2));
#pragma unroll
                for (int m = 0; m < 4; m++)
#pragma unroll
                    for (int n = 0; n < 2; n++)
                        mma8(acc[m][n], af + 4 * m, bh + 2 * n);
            }
        }

        if (c + 1 < NC) {
            float* st = sm + (buf ^ 1) * STGF;
#pragma unroll
            for (int it = 0; it < 4; it++) {
                const int idx = (row0 + it * 32) * 36 + c4;
                uint4 h, l;
                split4(av[it], h, l);
                *(uint4*)(st + AH + idx) = h;
                if (TERMS == 3) *(uint4*)(st + AL + idx) = l;
            }
#pragma unroll
            for (int it = 0; it < 2; it++) {
                const int idx = (row0 + it * 32) * 36 + c4;
                uint4 h, l;
                split4(bv[it], h, l);
                *(uint4*)(st + BH + idx) = h;
                *(uint4*)(st + BL + idx) = l;
            }
        }
        __syncthreads();
    }

    const int g = lane >> 2;
    const int t = lane & 3;
#pragma unroll
    for (int n = 0; n < 2; n++) {
        const int col = bn + wn * 16 + n * 8 + t * 2;
        float b0 = 0.f, b1 = 0.f;
        if (bias) { b0 = bias[col]; b1 = bias[col + 1]; }
#pragma unroll
        for (int m = 0; m < 4; m++) {
            const int r0 = bm + wm * 64 + m * 16 + g;
            float2 v0 = make_float2(acc[m][n][0] + b0, acc[m][n][1] + b1);
            float2 v1 = make_float2(acc[m][n][2] + b0, acc[m][n][3] + b1);
            *(float2*)(C + (long)r0 * N + col) = v0;
            *(float2*)(C + (long)(r0 + 8) * N + col) = v1;
        }
    }
}

template <int TERMS>
__global__ void __launch_bounds__(256, 2) tc_gemm(
    const float* __restrict__ A, const float* __restrict__ B,
    float* __restrict__ C, const float* __restrict__ bias,
    int N, int K, long sA, long sB, long sC)
{
    extern __shared__ float sm[];
    gemm_core<TERMS>(A + (long)blockIdx.z * sA, B + (long)blockIdx.z * sB,
                     C + (long)blockIdx.z * sC, bias, N, K, sm);
}

// Merged projections (tf32): z 0..2 = q,k,nk 3-term; z==3 = v 2-term.
struct ProjArgs {
    const float* in[4];
    const float* W[4];
    const float* bias[4];
    float* out[4];
};

__global__ void __launch_bounds__(256, 2) tc_proj(ProjArgs p)
{
    extern __shared__ float sm[];
    const int z = blockIdx.z;
    if (z != 3)
        gemm_core<3>(p.in[z], p.W[z], p.out[z], p.bias[z], D_, D_, sm);
    else
        gemm_core<2>(p.in[z], p.W[z], p.out[z], p.bias[z], D_, D_, sm);
}

// ---------------------------------------------------------------------------
// bf16x3 GEMM (hi/lo split; AhBh + AhBl + AlBh). CTA 128x64, K-chunk 32,
// 8 warps 2m x 4n, warp 64x16, mma.m16n8k16. Elementwise error ~2^-16.
// Stage bytes: Ah[128*80] Al[128*80] Bh[64*80] Bl[64*80] = 30720; x2 stages.
// ---------------------------------------------------------------------------
#define BF_AB 10240  // 128*80 bytes
#define BF_BB 5120   // 64*80 bytes
#define BF_STG 30720

__global__ void __launch_bounds__(256, 2) tc_gemm_bf(
    const float* __restrict__ A, const float* __restrict__ B,
    float* __restrict__ C, const float* __restrict__ bias,
    int N, int K, long sA, long sB, long sC)
{
    extern __shared__ char smc[];
    const uint32_t smb = smem_u32(smc);
    A += (long)blockIdx.z * sA;
    B += (long)blockIdx.z * sB;
    C += (long)blockIdx.z * sC;

    const int tid = threadIdx.x;
    const int lane = tid & 31;
    const int warp = tid >> 5;
    const int wm = warp >> 2;
    const int wn = warp & 3;
    const int bm = blockIdx.y * 128;
    const int bn = blockIdx.x * 64;

    const int row0 = tid >> 3;       // 0..31
    const int c4 = (tid & 7) << 2;   // element col 0..28
    const float* Ap = A + (long)(bm + row0) * K + c4;
    const float* Bp = B + (long)(bn + row0) * K + c4;

    // ldmatrix byte offsets (80B rows; 16B k8-halves)
    const uint32_t aOff = (uint32_t)(wm * 64 + (lane & 15)) * 80u + (lane & 16);
    const uint32_t bOff = (uint32_t)(wn * 16 + (lane & 7) + ((lane & 16) >> 1)) * 80u
                          + ((lane & 8) << 1) + 2u * BF_AB;

    float acc[4][2][4];
#pragma unroll
    for (int m = 0; m < 4; m++)
#pragma unroll
        for (int n = 0; n < 2; n++)
#pragma unroll
            for (int r = 0; r < 4; r++) acc[m][n][r] = 0.f;

    const int NC = K >> 5;

    // prologue: chunk 0 -> stage 0
    {
        float4 av[4], bv[2];
#pragma unroll
        for (int it = 0; it < 4; it++)
            av[it] = *(const float4*)(Ap + (long)(it * 32) * K);
#pragma unroll
        for (int it = 0; it < 2; it++)
            bv[it] = *(const float4*)(Bp + (long)(it * 32) * K);
#pragma unroll
        for (int it = 0; it < 4; it++) {
            const int idx = (row0 + it * 32) * 80 + c4 * 2;
            uint2 h, l;
            splitbf4(av[it], h, l);
            *(uint2*)(smc + idx) = h;
            *(uint2*)(smc + BF_AB + idx) = l;
        }
#pragma unroll
        for (int it = 0; it < 2; it++) {
            const int idx = (row0 + it * 32) * 80 + c4 * 2;
            uint2 h, l;
            splitbf4(bv[it], h, l);
            *(uint2*)(smc + 2 * BF_AB + idx) = h;
            *(uint2*)(smc + 2 * BF_AB + BF_BB + idx) = l;
        }
    }
    __syncthreads();

    for (int c = 0; c < NC; c++) {
        const int buf = c & 1;
        float4 av[4], bv[2];
        if (c + 1 < NC) {
            const int k0 = (c + 1) << 5;
#pragma unroll
            for (int it = 0; it < 4; it++)
                av[it] = *(const float4*)(Ap + (long)(it * 32) * K + k0);
#pragma unroll
            for (int it = 0; it < 2; it++)
                bv[it] = *(const float4*)(Bp + (long)(it * 32) * K + k0);
        }

        const uint32_t stB = smb + (uint32_t)buf * BF_STG;
        const uint32_t aH = stB + aOff;
        const uint32_t aL = aH + BF_AB;
        const uint32_t bH = stB + bOff;
        const uint32_t bL = bH + BF_BB;
#pragma unroll
        for (int s = 0; s < 2; s++) {          // two k16 steps per chunk
            const uint32_t ks = (uint32_t)s * 32;  // 16 bf16 = 32 bytes
            uint32_t bh[4], bl[4];
            ldsm4(bh, bH + ks);
            ldsm4(bl, bL + ks);
            uint32_t af[16];
#pragma unroll
            for (int m = 0; m < 4; m++)
                ldsm4(af + 4 * m, aH + ks + (uint32_t)(m * 16 * 80));
#pragma unroll
            for (int m = 0; m < 4; m++)
#pragma unroll
                for (int n = 0; n < 2; n++) {
                    mma16(acc[m][n], af + 4 * m, bh + 2 * n);
                    mma16(acc[m][n], af + 4 * m, bl + 2 * n);
                }
#pragma unroll
            for (int m = 0; m < 4; m++)
                ldsm4(af + 4 * m, aL + ks + (uint32_t)(m * 16 * 80));
#pragma unroll
            for (int m = 0; m < 4; m++)
#pragma unroll
                for (int n = 0; n < 2; n++)
                    mma16(acc[m][n], af + 4 * m, bh + 2 * n);
        }

        if (c + 1 < NC) {
            char* st = smc + (buf ^ 1) * BF_STG;
#pragma unroll
            for (int it = 0; it < 4; it++) {
                const int idx = (row0 + it * 32) * 80 + c4 * 2;
                uint2 h, l;
                splitbf4(av[it], h, l);
                *(uint2*)(st + idx) = h;
                *(uint2*)(st + BF_AB + idx) = l;
            }
#pragma unroll
            for (int it = 0; it < 2; it++) {
                const int idx = (row0 + it * 32) * 80 + c4 * 2;
                uint2 h, l;
                splitbf4(bv[it], h, l);
                *(uint2*)(st + 2 * BF_AB + idx) = h;
                *(uint2*)(st + 2 * BF_AB + BF_BB + idx) = l;
            }
        }
        __syncthreads();
    }

    const int g = lane >> 2;
    const int t = lane & 3;
#pragma unroll
    for (int n = 0; n < 2; n++) {
        const int col = bn + wn * 16 + n * 8 + t * 2;
        float b0 = 0.f, b1 = 0.f;
        if (bias) { b0 = bias[col]; b1 = bias[col + 1]; }
#pragma unroll
        for (int m = 0; m < 4; m++) {
            const int r0 = bm + wm * 64 + m * 16 + g;
            float2 v0 = make_float2(acc[m][n][0] + b0, acc[m][n][1] + b1);
            float2 v1 = make_float2(acc[m][n][2] + b0, acc[m][n][3] + b1);
            *(float2*)(C + (long)r0 * N + col) = v0;
            *(float2*)(C + (long)(r0 + 8) * N + col) = v1;
        }
    }
}

// ---------------------------------------------------------------------------
// Batched transpose: in [B][L][D] -> out [B][D][L]
// ---------------------------------------------------------------------------
__global__ void transpose_ld(const float* __restrict__ in, float* __restrict__ out)
{
    __shared__ float t[32][33];
    const int b = blockIdx.z;
    const int d0 = blockIdx.x * 32;
    const int l0 = blockIdx.y * 32;
    const int x = threadIdx.x;
    const int y = threadIdx.y;
    const float* ib = in + ((long)b * L_ + l0) * D_ + d0;
#pragma unroll
    for (int i = y; i < 32; i += 8) t[i][x] = ib[(long)i * D_ + x];
    __syncthreads();
    float* ob = out + ((long)b * D_ + d0) * L_ + l0;
#pragma unroll
    for (int i = y; i < 32; i += 8) ob[(long)i * L_ + x] = t[x][i];
}

// ---------------------------------------------------------------------------
// Fused attention via mma.sync (validated in R6/R8).
// ---------------------------------------------------------------------------
__global__ void __launch_bounds__(256, 2) attn_mma(
    const float* __restrict__ Q, const float* __restrict__ K,
    const float* __restrict__ V, const float* __restrict__ E,
    float* __restrict__ O)
{
    extern __shared__ float sh[];
    float* sQ = sh;                    // 128*68
    float* sK = sh + 128 * 68;         // 64*68
    float* sVh = sK + 64 * 68;         // [d][key]

    const int b = blockIdx.y / H_;
    const int h = blockIdx.y % H_;
    const int l0 = blockIdx.x * 128;
    const int tid = threadIdx.x;
    const int lane = tid & 31;
    const int w = tid >> 5;
    const int g = lane >> 2;
    const int t = lane & 3;

    const float* qb = Q + ((long)b * L_ + l0) * D_ + h * 64;
    const float* kb = K + (long)b * L_ * D_ + h * 64;
    const float* vb = V + (long)b * L_ * D_ + h * 64;
    const float* e0 = E + ((long)b * L_ + l0 + w * 16 + g) * L_;
    const float* e1 = e0 + 8 * L_;

#pragma unroll
    for (int it = 0; it < 8; it++) {
        int f = tid + it * 256;
        int row = f >> 4;
        int d4 = (f & 15) << 2;
        float4 v = *(const float4*)(qb + (long)row * D_ + d4);
        *(uint4*)(sQ + row * 68 + d4) = hi4(v);
    }

    const uint32_t sQa = smem_u32(sQ) +
        ((((uint32_t)(w * 16 + (lane & 15)) * 68u) + ((lane & 16) >> 2)) << 2);
    const uint32_t bPat =
        ((((uint32_t)((lane & 7) + ((lane & 16) >> 1)) * 68u) +
          ((lane & 8) >> 1)) << 2);
    const uint32_t sKa = smem_u32(sK) + bPat;
    const uint32_t sVha = smem_u32(sVh) + bPat;
    const uint32_t R16 = (16 * 68) << 2;

    float o[8][4];
#pragma unroll
    for (int j = 0; j < 8; j++)
#pragma unroll
        for (int r = 0; r < 4; r++) o[j][r] = 0.f;
    float m0 = -1e30f, m1 = -1e30f, sum0 = 0.f, sum1 = 0.f;

    for (int jb = 0; jb < 16; jb++) {
        __syncthreads();
#pragma unroll
        for (int it = 0; it < 4; it++) {
            int f = tid + it * 256;
            int key = f >> 4;
            int d4 = (f & 15) << 2;
            float4 v = *(const float4*)(kb + (long)(jb * 64 + key) * D_ + d4);
            *(uint4*)(sK + key * 68 + d4) = hi4(v);
        }
#pragma unroll
        for (int it = 0; it < 4; it++) {
            int f = tid + it * 256;
            int key = f >> 4;
            int d4 = (f & 15) << 2;
            float4 v = *(const float4*)(vb + (long)(jb * 64 + key) * D_ + d4);
            float vv[4] = {v.x, v.y, v.z, v.w};
#pragma unroll
            for (int i = 0; i < 4; i++)
                *(uint32_t*)(sVh + (d4 + i) * 68 + key) = f2tf32(vv[i]);
        }
        __syncthreads();

        float accS[8][4];
#pragma unroll
        for (int j = 0; j < 8; j++)
#pragma unroll
            for (int r = 0; r < 4; r++) accS[j][r] = 0.f;
#pragma unroll
        for (int s = 0; s < 8; s++) {
            const uint32_t ks = (uint32_t)s * 32;
            uint32_t af[4], bf[16];
            ldsm4(af, sQa + ks);
            ldsm4(bf + 0,  sKa + ks);
            ldsm4(bf + 4,  sKa + ks + R16);
            ldsm4(bf + 8,  sKa + ks + 2 * R16);
            ldsm4(bf + 12, sKa + ks + 3 * R16);
#pragma unroll
            for (int j = 0; j < 8; j++) mma8(accS[j], af, bf + 2 * j);
        }

#pragma unroll
        for (int j = 0; j < 8; j++) {
            const int col = jb * 64 + 8 * j + 2 * t;
            float2 ea = *(const float2*)(e0 + col);
            float2 ebv = *(const float2*)(e1 + col);
            accS[j][0] = (accS[j][0] + ea.x) * 0.0625f;
            accS[j][1] = (accS[j][1] + ea.y) * 0.0625f;
            accS[j][2] = (accS[j][2] + ebv.x) * 0.0625f;
            accS[j][3] = (accS[j][3] + ebv.y) * 0.0625f;
        }

        float mx0 = -1e30f, mx1 = -1e30f;
#pragma unroll
        for (int j = 0; j < 8; j++) {
            mx0 = fmaxf(mx0, fmaxf(accS[j][0], accS[j][1]));
            mx1 = fmaxf(mx1, fmaxf(accS[j][2], accS[j][3]));
        }
#pragma unroll
        for (int off = 1; off <= 2; off <<= 1) {
            mx0 = fmaxf(mx0, __shfl_xor_sync(0xffffffffu, mx0, off));
            mx1 = fmaxf(mx1, __shfl_xor_sync(0xffffffffu, mx1, off));
        }
        const float nm0 = fmaxf(m0, mx0), nm1 = fmaxf(m1, mx1);
        const float sc0 = __expf(m0 - nm0), sc1 = __expf(m1 - nm1);
        float rs0 = 0.f, rs1 = 0.f;
#pragma unroll
        for (int j = 0; j < 8; j++) {
            accS[j][0] = __expf(accS[j][0] - nm0);
            accS[j][1] = __expf(accS[j][1] - nm0);
            accS[j][2] = __expf(accS[j][2] - nm1);
            accS[j][3] = __expf(accS[j][3] - nm1);
            rs0 += accS[j][0] + accS[j][1];
            rs1 += accS[j][2] + accS[j][3];
        }
#pragma unroll
        for (int off = 1; off <= 2; off <<= 1) {
            rs0 += __shfl_xor_sync(0xffffffffu, rs0, off);
            rs1 += __shfl_xor_sync(0xffffffffu, rs1, off);
        }
        sum0 = sum0 * sc0 + rs0;
        sum1 = sum1 * sc1 + rs1;
        m0 = nm0; m1 = nm1;
#pragma unroll
        for (int j = 0; j < 8; j++) {
            o[j][0] *= sc0; o[j][1] *= sc0;
            o[j][2] *= sc1; o[j][3] *= sc1;
        }

        const int sl0 = (lane & ~3) | (t >> 1);
        const int sl2 = sl0 + 2;
#pragma unroll
        for (int kt = 0; kt < 8; kt++) {
            float p00 = __shfl_sync(0xffffffffu, accS[kt][0], sl0);
            float p01 = __shfl_sync(0xffffffffu, accS[kt][1], sl0);
            float p20 = __shfl_sync(0xffffffffu, accS[kt][0], sl2);
            float p21 = __shfl_sync(0xffffffffu, accS[kt][1], sl2);
            float p10 = __shfl_sync(0xffffffffu, accS[kt][2], sl0);
            float p11 = __shfl_sync(0xffffffffu, accS[kt][3], sl0);
            float p30 = __shfl_sync(0xffffffffu, accS[kt][2], sl2);
            float p31 = __shfl_sync(0xffffffffu, accS[kt][3], sl2);
            float a0 = (t & 1) ? p01 : p00;
            float a1 = (t & 1) ? p11 : p10;
            float a2 = (t & 1) ? p21 : p20;
            float a3 = (t & 1) ? p31 : p30;
            uint32_t ah[4];
            ah[0] = f2tf32(a0); ah[1] = f2tf32(a1);
            ah[2] = f2tf32(a2); ah[3] = f2tf32(a3);

            const uint32_t ks = (uint32_t)kt * 32;
            uint32_t bvr[16];
            ldsm4(bvr + 0,  sVha + ks);
            ldsm4(bvr + 4,  sVha + ks + R16);
            ldsm4(bvr + 8,  sVha + ks + 2 * R16);
            ldsm4(bvr + 12, sVha + ks + 3 * R16);
#pragma unroll
            for (int j = 0; j < 8; j++)
                mma8(o[j], ah, bvr + 2 * j);
        }
    }

    const float inv0 = 1.f / sum0, inv1 = 1.f / sum1;
    float* ob = O + ((long)b * L_ + l0 + w * 16) * D_ + h * 64;
#pragma unroll
    for (int j = 0; j < 8; j++) {
        const int col = 8 * j + 2 * t;
        *(float2*)(ob + (long)g * D_ + col) =
            make_float2(o[j][0] * inv0, o[j][1] * inv0);
        *(float2*)(ob + (long)(g + 8) * D_ + col) =
            make_float2(o[j][2] * inv1, o[j][3] * inv1);
    }
}

// ---------------------------------------------------------------------------
extern "C" void kernel_launch(void* const* d_in, const int* in_sizes, int n_in,
                              void* d_out, int out_size)
{
    const float* query = (const float*)d_in[0];
    const float* key   = (const float*)d_in[1];
    const float* value = (const float*)d_in[2];
    const float* news  = (const float*)d_in[3];
    const float* Wq = (const float*)d_in[4];
    const float* bq = (const float*)d_in[5];
    const float* Wk = (const float*)d_in[6];
    const float* bk = (const float*)d_in[7];
    const float* Wv = (const float*)d_in[8];
    const float* bv = (const float*)d_in[9];
    const float* Wn = (const float*)d_in[10];
    const float* bn = (const float*)d_in[11];
    const float* Wo = (const float*)d_in[12];
    const float* bo = (const float*)d_in[13];
    // d_in[14] = pos. Mathematically irrelevant (swapaxes of swapped enh == enh).

    float *pq, *pk, *pv, *pn, *pnkT, *pG, *pT, *penh, *patt;
    cudaGetSymbolAddress((void**)&pq,   g_q);
    cudaGetSymbolAddress((void**)&pk,   g_k);
    cudaGetSymbolAddress((void**)&pv,   g_v);
    cudaGetSymbolAddress((void**)&pn,   g_n);
    cudaGetSymbolAddress((void**)&pnkT, g_nkT);
    cudaGetSymbolAddress((void**)&pG,   g_G);
    cudaGetSymbolAddress((void**)&pT,   g_T);
    cudaGetSymbolAddress((void**)&penh, g_enh);
    cudaGetSymbolAddress((void**)&patt, g_att);

    const int M = B_ * L_;  // 8192
    dim3 blk(256);
    const int smem3 = 2 * (2 * A_FL + 2 * B_FL) * 4;  // 110592
    const int smem2 = 2 * (A_FL + 2 * B_FL) * 4;      // 73728
    const int smemBF = 2 * BF_STG;                    // 61440
    cudaFuncSetAttribute(tc_proj,    cudaFuncAttributeMaxDynamicSharedMemorySize, smem3);
    cudaFuncSetAttribute(tc_gemm<2>, cudaFuncAttributeMaxDynamicSharedMemorySize, smem2);
    cudaFuncSetAttribute(tc_gemm_bf, cudaFuncAttributeMaxDynamicSharedMemorySize, smemBF);

    // all 4 projections in one launch (z: 0=q, 1=k, 2=nk tf32x3; 3=v tf32x2)
    ProjArgs pa;
    pa.in[0] = query; pa.in[1] = key; pa.in[2] = news; pa.in[3] = value;
    pa.W[0] = Wq; pa.W[1] = Wk; pa.W[2] = Wn; pa.W[3] = Wv;
    pa.bias[0] = bq; pa.bias[1] = bk; pa.bias[2] = bn; pa.bias[3] = bv;
    pa.out[0] = pq; pa.out[1] = pk; pa.out[2] = pn; pa.out[3] = pv;
    tc_proj<<<dim3(D_ / 64, M / 128, 4), blk, smem3>>>(pa);

    // enh = q (nk^T nk) k^T (bf16x3 on the whole chain)
    transpose_ld<<<dim3(D_ / 32, L_ / 32, B_), dim3(32, 8)>>>(pn, pnkT);
    tc_gemm_bf<<<dim3(D_ / 64, D_ / 128, B_), blk, smemBF>>>(pnkT, pnkT, pG, nullptr,
        D_, L_, (long)D_ * L_, (long)D_ * L_, (long)D_ * D_);
    tc_gemm_bf<<<dim3(D_ / 64, L_ / 128, B_), blk, smemBF>>>(pq, pG, pT, nullptr,
        D_, D_, (long)L_ * D_, (long)D_ * D_, (long)L_ * D_);
    tc_gemm_bf<<<dim3(L_ / 64, L_ / 128, B_), blk, smemBF>>>(pT, pk, penh, nullptr,
        L_, D_, (long)L_ * D_, (long)L_ * D_, (long)L_ * L_);

    // fused attention
    const int attn_smem = (128 * 68 + 2 * 64 * 68) * 4;  // 69632
    cudaFuncSetAttribute(attn_mma, cudaFuncAttributeMaxDynamicSharedMemorySize,
                         attn_smem);
    attn_mma<<<dim3(L_ / 128, B_ * H_), blk, attn_smem>>>(pq, pk, pv, penh, patt);

    // output projection (tf32 2-term) -> d_out
    tc_gemm<2><<<dim3(D_ / 64, M / 128, 1), blk, smem2>>>(patt, Wo, (float*)d_out, bo,
                                                          D_, D_, 0, 0, 0);
}

// round 10
// speedup vs baseline: 1.3208x; 1.1648x over previous
#include <cuda_runtime.h>
#include <cuda_bf16.h>
#include <stdint.h>

#define B_ 8
#define L_ 1024
#define D_ 768
#define H_ 12

// ---------------- scratch (device globals; no allocations allowed) ----------
__device__ float g_q[B_ * L_ * D_];
__device__ float g_k[B_ * L_ * D_];
__device__ float g_v[B_ * L_ * D_];
__device__ float g_n[B_ * L_ * D_];
__device__ float g_nkT[B_ * D_ * L_];
__device__ float g_G[B_ * D_ * D_];
__device__ float g_T[B_ * L_ * D_];
__device__ float g_enh[(long)B_ * L_ * L_];
__device__ float g_att[B_ * L_ * D_];

// ---------------- helpers ----------------------------------------------------
__device__ __forceinline__ uint32_t smem_u32(const void* p) {
    uint32_t a;
    asm("{ .reg .u64 t; cvta.to.shared.u64 t, %1; cvt.u32.u64 %0, t; }"
        : "=r"(a) : "l"(p));
    return a;
}
__device__ __forceinline__ uint32_t f2tf32(float x) {
    uint32_t r;
    asm("cvt.rna.tf32.f32 %0, %1;" : "=r"(r) : "f"(x));
    return r;
}
__device__ __forceinline__ uint4 hi4(float4 a) {
    uint4 h;
    h.x = f2tf32(a.x); h.y = f2tf32(a.y);
    h.z = f2tf32(a.z); h.w = f2tf32(a.w);
    return h;
}
__device__ __forceinline__ void ldsm4(uint32_t* r, uint32_t addr) {
    asm volatile("ldmatrix.sync.aligned.m8n8.x4.shared.b16 {%0,%1,%2,%3}, [%4];"
                 : "=r"(r[0]), "=r"(r[1]), "=r"(r[2]), "=r"(r[3]) : "r"(addr));
}
__device__ __forceinline__ void mma8(float* d, const uint32_t* a, const uint32_t* b) {
    asm volatile(
        "mma.sync.aligned.m16n8k8.row.col.f32.tf32.tf32.f32 "
        "{%0,%1,%2,%3}, {%4,%5,%6,%7}, {%8,%9}, {%0,%1,%2,%3};"
        : "+f"(d[0]), "+f"(d[1]), "+f"(d[2]), "+f"(d[3])
        : "r"(a[0]), "r"(a[1]), "r"(a[2]), "r"(a[3]), "r"(b[0]), "r"(b[1]));
}
__device__ __forceinline__ void mma16(float* d, const uint32_t* a, const uint32_t* b) {
    asm volatile(
        "mma.sync.aligned.m16n8k16.row.col.f32.bf16.bf16.f32 "
        "{%0,%1,%2,%3}, {%4,%5,%6,%7}, {%8,%9}, {%0,%1,%2,%3};"
        : "+f"(d[0]), "+f"(d[1]), "+f"(d[2]), "+f"(d[3])
        : "r"(a[0]), "r"(a[1]), "r"(a[2]), "r"(a[3]), "r"(b[0]), "r"(b[1]));
}
// bf16 2-level split of 4 floats -> hi(4xbf16 as uint2), lo(uint2)
__device__ __forceinline__ void splitbf4(float4 a, uint2& h, uint2& l) {
    float e[4] = {a.x, a.y, a.z, a.w};
    uint16_t hh[4], ll[4];
#pragma unroll
    for (int i = 0; i < 4; i++) {
        __nv_bfloat16 bh = __float2bfloat16_rn(e[i]);
        float hf = __bfloat162float(bh);
        __nv_bfloat16 bl = __float2bfloat16_rn(e[i] - hf);
        hh[i] = *reinterpret_cast<uint16_t*>(&bh);
        ll[i] = *reinterpret_cast<uint16_t*>(&bl);
    }
    h.x = (uint32_t)hh[0] | ((uint32_t)hh[1] << 16);
    h.y = (uint32_t)hh[2] | ((uint32_t)hh[3] << 16);
    l.x = (uint32_t)ll[0] | ((uint32_t)ll[1] << 16);
    l.y = (uint32_t)ll[2] | ((uint32_t)ll[3] << 16);
}

// ---------------------------------------------------------------------------
// bf16x3 GEMM core (hi/lo split; AhBh + AhBl + AlBh). Elementwise err ~2^-16.
// C[m,n] = sum_k A[m,k]*B[n,k] (+bias[n]).
// CTA 128x64, K-chunk 32, 8 warps 2m x 4n, warp 64x16, mma.m16n8k16.
// Stage bytes: Ah[128*80] Al[128*80] Bh[64*80] Bl[64*80] = 30720; x2 stages.
// 118 regs, 61.4KB smem -> 2 CTAs/SM.
// ---------------------------------------------------------------------------
#define BF_AB 10240  // 128*80 bytes
#define BF_BB 5120   // 64*80 bytes
#define BF_STG 30720

__device__ __forceinline__ void bf_core(
    const float* __restrict__ A, const float* __restrict__ B,
    float* __restrict__ C, const float* __restrict__ bias,
    int N, int K, char* smc)
{
    const uint32_t smb = smem_u32(smc);

    const int tid = threadIdx.x;
    const int lane = tid & 31;
    const int warp = tid >> 5;
    const int wm = warp >> 2;
    const int wn = warp & 3;
    const int bm = blockIdx.y * 128;
    const int bn = blockIdx.x * 64;

    const int row0 = tid >> 3;       // 0..31
    const int c4 = (tid & 7) << 2;   // element col 0..28
    const float* Ap = A + (long)(bm + row0) * K + c4;
    const float* Bp = B + (long)(bn + row0) * K + c4;

    // ldmatrix byte offsets (80B rows; 16B k8-halves)
    const uint32_t aOff = (uint32_t)(wm * 64 + (lane & 15)) * 80u + (lane & 16);
    const uint32_t bOff = (uint32_t)(wn * 16 + (lane & 7) + ((lane & 16) >> 1)) * 80u
                          + ((lane & 8) << 1) + 2u * BF_AB;

    float acc[4][2][4];
#pragma unroll
    for (int m = 0; m < 4; m++)
#pragma unroll
        for (int n = 0; n < 2; n++)
#pragma unroll
            for (int r = 0; r < 4; r++) acc[m][n][r] = 0.f;

    const int NC = K >> 5;

    // prologue: chunk 0 -> stage 0
    {
        float4 av[4], bv[2];
#pragma unroll
        for (int it = 0; it < 4; it++)
            av[it] = *(const float4*)(Ap + (long)(it * 32) * K);
#pragma unroll
        for (int it = 0; it < 2; it++)
            bv[it] = *(const float4*)(Bp + (long)(it * 32) * K);
#pragma unroll
        for (int it = 0; it < 4; it++) {
            const int idx = (row0 + it * 32) * 80 + c4 * 2;
            uint2 h, l;
            splitbf4(av[it], h, l);
            *(uint2*)(smc + idx) = h;
            *(uint2*)(smc + BF_AB + idx) = l;
        }
#pragma unroll
        for (int it = 0; it < 2; it++) {
            const int idx = (row0 + it * 32) * 80 + c4 * 2;
            uint2 h, l;
            splitbf4(bv[it], h, l);
            *(uint2*)(smc + 2 * BF_AB + idx) = h;
            *(uint2*)(smc + 2 * BF_AB + BF_BB + idx) = l;
        }
    }
    __syncthreads();

    for (int c = 0; c < NC; c++) {
        const int buf = c & 1;
        float4 av[4], bv[2];
        if (c + 1 < NC) {
            const int k0 = (c + 1) << 5;
#pragma unroll
            for (int it = 0; it < 4; it++)
                av[it] = *(const float4*)(Ap + (long)(it * 32) * K + k0);
#pragma unroll
            for (int it = 0; it < 2; it++)
                bv[it] = *(const float4*)(Bp + (long)(it * 32) * K + k0);
        }

        const uint32_t stB = smb + (uint32_t)buf * BF_STG;
        const uint32_t aH = stB + aOff;
        const uint32_t aL = aH + BF_AB;
        const uint32_t bH = stB + bOff;
        const uint32_t bL = bH + BF_BB;
#pragma unroll
        for (int s = 0; s < 2; s++) {          // two k16 steps per chunk
            const uint32_t ks = (uint32_t)s * 32;  // 16 bf16 = 32 bytes
            uint32_t bh[4], bl[4];
            ldsm4(bh, bH + ks);
            ldsm4(bl, bL + ks);
            uint32_t af[16];
#pragma unroll
            for (int m = 0; m < 4; m++)
                ldsm4(af + 4 * m, aH + ks + (uint32_t)(m * 16 * 80));
#pragma unroll
            for (int m = 0; m < 4; m++)
#pragma unroll
                for (int n = 0; n < 2; n++) {
                    mma16(acc[m][n], af + 4 * m, bh + 2 * n);
                    mma16(acc[m][n], af + 4 * m, bl + 2 * n);
                }
#pragma unroll
            for (int m = 0; m < 4; m++)
                ldsm4(af + 4 * m, aL + ks + (uint32_t)(m * 16 * 80));
#pragma unroll
            for (int m = 0; m < 4; m++)
#pragma unroll
                for (int n = 0; n < 2; n++)
                    mma16(acc[m][n], af + 4 * m, bh + 2 * n);
        }

        if (c + 1 < NC) {
            char* st = smc + (buf ^ 1) * BF_STG;
#pragma unroll
            for (int it = 0; it < 4; it++) {
                const int idx = (row0 + it * 32) * 80 + c4 * 2;
                uint2 h, l;
                splitbf4(av[it], h, l);
                *(uint2*)(st + idx) = h;
                *(uint2*)(st + BF_AB + idx) = l;
            }
#pragma unroll
            for (int it = 0; it < 2; it++) {
                const int idx = (row0 + it * 32) * 80 + c4 * 2;
                uint2 h, l;
                splitbf4(bv[it], h, l);
                *(uint2*)(st + 2 * BF_AB + idx) = h;
                *(uint2*)(st + 2 * BF_AB + BF_BB + idx) = l;
            }
        }
        __syncthreads();
    }

    const int g = lane >> 2;
    const int t = lane & 3;
#pragma unroll
    for (int n = 0; n < 2; n++) {
        const int col = bn + wn * 16 + n * 8 + t * 2;
        float b0 = 0.f, b1 = 0.f;
        if (bias) { b0 = bias[col]; b1 = bias[col + 1]; }
#pragma unroll
        for (int m = 0; m < 4; m++) {
            const int r0 = bm + wm * 64 + m * 16 + g;
            float2 v0 = make_float2(acc[m][n][0] + b0, acc[m][n][1] + b1);
            float2 v1 = make_float2(acc[m][n][2] + b0, acc[m][n][3] + b1);
            *(float2*)(C + (long)r0 * N + col) = v0;
            *(float2*)(C + (long)(r0 + 8) * N + col) = v1;
        }
    }
}

__global__ void __launch_bounds__(256, 2) tc_gemm_bf(
    const float* __restrict__ A, const float* __restrict__ B,
    float* __restrict__ C, const float* __restrict__ bias,
    int N, int K, long sA, long sB, long sC)
{
    extern __shared__ char smc[];
    bf_core(A + (long)blockIdx.z * sA, B + (long)blockIdx.z * sB,
            C + (long)blockIdx.z * sC, bias, N, K, smc);
}

// Merged projections (all bf16x3): z selects (input, W, bias, output).
struct ProjArgs {
    const float* in[4];
    const float* W[4];
    const float* bias[4];
    float* out[4];
};

__global__ void __launch_bounds__(256, 2) tc_proj(ProjArgs p)
{
    extern __shared__ char smc[];
    const int z = blockIdx.z;
    bf_core(p.in[z], p.W[z], p.out[z], p.bias[z], D_, D_, smc);
}

// ---------------------------------------------------------------------------
// Batched transpose: in [B][L][D] -> out [B][D][L]
// ---------------------------------------------------------------------------
__global__ void transpose_ld(const float* __restrict__ in, float* __restrict__ out)
{
    __shared__ float t[32][33];
    const int b = blockIdx.z;
    const int d0 = blockIdx.x * 32;
    const int l0 = blockIdx.y * 32;
    const int x = threadIdx.x;
    const int y = threadIdx.y;
    const float* ib = in + ((long)b * L_ + l0) * D_ + d0;
#pragma unroll
    for (int i = y; i < 32; i += 8) t[i][x] = ib[(long)i * D_ + x];
    __syncthreads();
    float* ob = out + ((long)b * D_ + d0) * L_ + l0;
#pragma unroll
    for (int i = y; i < 32; i += 8) ob[(long)i * L_ + x] = t[x][i];
}

// ---------------------------------------------------------------------------
// Fused attention via mma.sync (validated R6/R8/R9).
//   S = QK^T (1x tf32) ; S = (S+E)/16 ; online softmax ; O = P V (1x tf32).
// ---------------------------------------------------------------------------
__global__ void __launch_bounds__(256, 2) attn_mma(
    const float* __restrict__ Q, const float* __restrict__ K,
    const float* __restrict__ V, const float* __restrict__ E,
    float* __restrict__ O)
{
    extern __shared__ float sh[];
    float* sQ = sh;                    // 128*68
    float* sK = sh + 128 * 68;         // 64*68
    float* sVh = sK + 64 * 68;         // [d][key]

    const int b = blockIdx.y / H_;
    const int h = blockIdx.y % H_;
    const int l0 = blockIdx.x * 128;
    const int tid = threadIdx.x;
    const int lane = tid & 31;
    const int w = tid >> 5;
    const int g = lane >> 2;
    const int t = lane & 3;

    const float* qb = Q + ((long)b * L_ + l0) * D_ + h * 64;
    const float* kb = K + (long)b * L_ * D_ + h * 64;
    const float* vb = V + (long)b * L_ * D_ + h * 64;
    const float* e0 = E + ((long)b * L_ + l0 + w * 16 + g) * L_;
    const float* e1 = e0 + 8 * L_;

#pragma unroll
    for (int it = 0; it < 8; it++) {
        int f = tid + it * 256;
        int row = f >> 4;
        int d4 = (f & 15) << 2;
        float4 v = *(const float4*)(qb + (long)row * D_ + d4);
        *(uint4*)(sQ + row * 68 + d4) = hi4(v);
    }

    const uint32_t sQa = smem_u32(sQ) +
        ((((uint32_t)(w * 16 + (lane & 15)) * 68u) + ((lane & 16) >> 2)) << 2);
    const uint32_t bPat =
        ((((uint32_t)((lane & 7) + ((lane & 16) >> 1)) * 68u) +
          ((lane & 8) >> 1)) << 2);
    const uint32_t sKa = smem_u32(sK) + bPat;
    const uint32_t sVha = smem_u32(sVh) + bPat;
    const uint32_t R16 = (16 * 68) << 2;

    float o[8][4];
#pragma unroll
    for (int j = 0; j < 8; j++)
#pragma unroll
        for (int r = 0; r < 4; r++) o[j][r] = 0.f;
    float m0 = -1e30f, m1 = -1e30f, sum0 = 0.f, sum1 = 0.f;

    for (int jb = 0; jb < 16; jb++) {
        __syncthreads();
#pragma unroll
        for (int it = 0; it < 4; it++) {
            int f = tid + it * 256;
            int key = f >> 4;
            int d4 = (f & 15) << 2;
            float4 v = *(const float4*)(kb + (long)(jb * 64 + key) * D_ + d4);
            *(uint4*)(sK + key * 68 + d4) = hi4(v);
        }
#pragma unroll
        for (int it = 0; it < 4; it++) {
            int f = tid + it * 256;
            int key = f >> 4;
            int d4 = (f & 15) << 2;
            float4 v = *(const float4*)(vb + (long)(jb * 64 + key) * D_ + d4);
            float vv[4] = {v.x, v.y, v.z, v.w};
#pragma unroll
            for (int i = 0; i < 4; i++)
                *(uint32_t*)(sVh + (d4 + i) * 68 + key) = f2tf32(vv[i]);
        }
        __syncthreads();

        float accS[8][4];
#pragma unroll
        for (int j = 0; j < 8; j++)
#pragma unroll
            for (int r = 0; r < 4; r++) accS[j][r] = 0.f;
#pragma unroll
        for (int s = 0; s < 8; s++) {
            const uint32_t ks = (uint32_t)s * 32;
            uint32_t af[4], bf[16];
            ldsm4(af, sQa + ks);
            ldsm4(bf + 0,  sKa + ks);
            ldsm4(bf + 4,  sKa + ks + R16);
            ldsm4(bf + 8,  sKa + ks + 2 * R16);
            ldsm4(bf + 12, sKa + ks + 3 * R16);
#pragma unroll
            for (int j = 0; j < 8; j++) mma8(accS[j], af, bf + 2 * j);
        }

#pragma unroll
        for (int j = 0; j < 8; j++) {
            const int col = jb * 64 + 8 * j + 2 * t;
            float2 ea = *(const float2*)(e0 + col);
            float2 ebv = *(const float2*)(e1 + col);
            accS[j][0] = (accS[j][0] + ea.x) * 0.0625f;
            accS[j][1] = (accS[j][1] + ea.y) * 0.0625f;
            accS[j][2] = (accS[j][2] + ebv.x) * 0.0625f;
            accS[j][3] = (accS[j][3] + ebv.y) * 0.0625f;
        }

        float mx0 = -1e30f, mx1 = -1e30f;
#pragma unroll
        for (int j = 0; j < 8; j++) {
            mx0 = fmaxf(mx0, fmaxf(accS[j][0], accS[j][1]));
            mx1 = fmaxf(mx1, fmaxf(accS[j][2], accS[j][3]));
        }
#pragma unroll
        for (int off = 1; off <= 2; off <<= 1) {
            mx0 = fmaxf(mx0, __shfl_xor_sync(0xffffffffu, mx0, off));
            mx1 = fmaxf(mx1, __shfl_xor_sync(0xffffffffu, mx1, off));
        }
        const float nm0 = fmaxf(m0, mx0), nm1 = fmaxf(m1, mx1);
        const float sc0 = __expf(m0 - nm0), sc1 = __expf(m1 - nm1);
        float rs0 = 0.f, rs1 = 0.f;
#pragma unroll
        for (int j = 0; j < 8; j++) {
            accS[j][0] = __expf(accS[j][0] - nm0);
            accS[j][1] = __expf(accS[j][1] - nm0);
            accS[j][2] = __expf(accS[j][2] - nm1);
            accS[j][3] = __expf(accS[j][3] - nm1);
            rs0 += accS[j][0] + accS[j][1];
            rs1 += accS[j][2] + accS[j][3];
        }
#pragma unroll
        for (int off = 1; off <= 2; off <<= 1) {
            rs0 += __shfl_xor_sync(0xffffffffu, rs0, off);
            rs1 += __shfl_xor_sync(0xffffffffu, rs1, off);
        }
        sum0 = sum0 * sc0 + rs0;
        sum1 = sum1 * sc1 + rs1;
        m0 = nm0; m1 = nm1;
#pragma unroll
        for (int j = 0; j < 8; j++) {
            o[j][0] *= sc0; o[j][1] *= sc0;
            o[j][2] *= sc1; o[j][3] *= sc1;
        }

        const int sl0 = (lane & ~3) | (t >> 1);
        const int sl2 = sl0 + 2;
#pragma unroll
        for (int kt = 0; kt < 8; kt++) {
            float p00 = __shfl_sync(0xffffffffu, accS[kt][0], sl0);
            float p01 = __shfl_sync(0xffffffffu, accS[kt][1], sl0);
            float p20 = __shfl_sync(0xffffffffu, accS[kt][0], sl2);
            float p21 = __shfl_sync(0xffffffffu, accS[kt][1], sl2);
            float p10 = __shfl_sync(0xffffffffu, accS[kt][2], sl0);
            float p11 = __shfl_sync(0xffffffffu, accS[kt][3], sl0);
            float p30 = __shfl_sync(0xffffffffu, accS[kt][2], sl2);
            float p31 = __shfl_sync(0xffffffffu, accS[kt][3], sl2);
            float a0 = (t & 1) ? p01 : p00;
            float a1 = (t & 1) ? p11 : p10;
            float a2 = (t & 1) ? p21 : p20;
            float a3 = (t & 1) ? p31 : p30;
            uint32_t ah[4];
            ah[0] = f2tf32(a0); ah[1] = f2tf32(a1);
            ah[2] = f2tf32(a2); ah[3] = f2tf32(a3);

            const uint32_t ks = (uint32_t)kt * 32;
            uint32_t bvr[16];
            ldsm4(bvr + 0,  sVha + ks);
            ldsm4(bvr + 4,  sVha + ks + R16);
            ldsm4(bvr + 8,  sVha + ks + 2 * R16);
            ldsm4(bvr + 12, sVha + ks + 3 * R16);
#pragma unroll
            for (int j = 0; j < 8; j++)
                mma8(o[j], ah, bvr + 2 * j);
        }
    }

    const float inv0 = 1.f / sum0, inv1 = 1.f / sum1;
    float* ob = O + ((long)b * L_ + l0 + w * 16) * D_ + h * 64;
#pragma unroll
    for (int j = 0; j < 8; j++) {
        const int col = 8 * j + 2 * t;
        *(float2*)(ob + (long)g * D_ + col) =
            make_float2(o[j][0] * inv0, o[j][1] * inv0);
        *(float2*)(ob + (long)(g + 8) * D_ + col) =
            make_float2(o[j][2] * inv1, o[j][3] * inv1);
    }
}

// ---------------------------------------------------------------------------
extern "C" void kernel_launch(void* const* d_in, const int* in_sizes, int n_in,
                              void* d_out, int out_size)
{
    const float* query = (const float*)d_in[0];
    const float* key   = (const float*)d_in[1];
    const float* value = (const float*)d_in[2];
    const float* news  = (const float*)d_in[3];
    const float* Wq = (const float*)d_in[4];
    const float* bq = (const float*)d_in[5];
    const float* Wk = (const float*)d_in[6];
    const float* bk = (const float*)d_in[7];
    const float* Wv = (const float*)d_in[8];
    const float* bv = (const float*)d_in[9];
    const float* Wn = (const float*)d_in[10];
    const float* bn = (const float*)d_in[11];
    const float* Wo = (const float*)d_in[12];
    const float* bo = (const float*)d_in[13];
    // d_in[14] = pos. Mathematically irrelevant (swapaxes of swapped enh == enh).

    float *pq, *pk, *pv, *pn, *pnkT, *pG, *pT, *penh, *patt;
    cudaGetSymbolAddress((void**)&pq,   g_q);
    cudaGetSymbolAddress((void**)&pk,   g_k);
    cudaGetSymbolAddress((void**)&pv,   g_v);
    cudaGetSymbolAddress((void**)&pn,   g_n);
    cudaGetSymbolAddress((void**)&pnkT, g_nkT);
    cudaGetSymbolAddress((void**)&pG,   g_G);
    cudaGetSymbolAddress((void**)&pT,   g_T);
    cudaGetSymbolAddress((void**)&penh, g_enh);
    cudaGetSymbolAddress((void**)&patt, g_att);

    const int M = B_ * L_;  // 8192
    dim3 blk(256);
    const int smemBF = 2 * BF_STG;  // 61440
    cudaFuncSetAttribute(tc_proj,    cudaFuncAttributeMaxDynamicSharedMemorySize, smemBF);
    cudaFuncSetAttribute(tc_gemm_bf, cudaFuncAttributeMaxDynamicSharedMemorySize, smemBF);

    // all 4 projections in one launch (all bf16x3)
    ProjArgs pa;
    pa.in[0] = query; pa.in[1] = key; pa.in[2] = news; pa.in[3] = value;
    pa.W[0] = Wq; pa.W[1] = Wk; pa.W[2] = Wn; pa.W[3] = Wv;
    pa.bias[0] = bq; pa.bias[1] = bk; pa.bias[2] = bn; pa.bias[3] = bv;
    pa.out[0] = pq; pa.out[1] = pk; pa.out[2] = pn; pa.out[3] = pv;
    tc_proj<<<dim3(D_ / 64, M / 128, 4), blk, smemBF>>>(pa);

    // enh = q (nk^T nk) k^T (bf16x3 chain)
    transpose_ld<<<dim3(D_ / 32, L_ / 32, B_), dim3(32, 8)>>>(pn, pnkT);
    tc_gemm_bf<<<dim3(D_ / 64, D_ / 128, B_), blk, smemBF>>>(pnkT, pnkT, pG, nullptr,
        D_, L_, (long)D_ * L_, (long)D_ * L_, (long)D_ * D_);
    tc_gemm_bf<<<dim3(D_ / 64, L_ / 128, B_), blk, smemBF>>>(pq, pG, pT, nullptr,
        D_, D_, (long)L_ * D_, (long)D_ * D_, (long)L_ * D_);
    tc_gemm_bf<<<dim3(L_ / 64, L_ / 128, B_), blk, smemBF>>>(pT, pk, penh, nullptr,
        L_, D_, (long)L_ * D_, (long)L_ * D_, (long)L_ * L_);

    // fused attention
    const int attn_smem = (128 * 68 + 2 * 64 * 68) * 4;  // 69632
    cudaFuncSetAttribute(attn_mma, cudaFuncAttributeMaxDynamicSharedMemorySize,
                         attn_smem);
    attn_mma<<<dim3(L_ / 128, B_ * H_), blk, attn_smem>>>(pq, pk, pv, penh, patt);

    // output projection (bf16x3) -> d_out
    tc_gemm_bf<<<dim3(D_ / 64, M / 128, 1), blk, smemBF>>>(patt, Wo, (float*)d_out, bo,
                                                           D_, D_, 0, 0, 0);
}

// round 11
// speedup vs baseline: 1.4742x; 1.1161x over previous
#include <cuda_runtime.h>
#include <cuda_bf16.h>
#include <stdint.h>

#define B_ 8
#define L_ 1024
#define D_ 768
#define H_ 12

// ---------------- scratch (device globals; no allocations allowed) ----------
__device__ float g_q[B_ * L_ * D_];
__device__ float g_k[B_ * L_ * D_];
__device__ float g_v[B_ * L_ * D_];
__device__ float g_n[B_ * L_ * D_];
__device__ float g_nkT[B_ * D_ * L_];
__device__ float g_G[B_ * D_ * D_];
__device__ float g_T[B_ * L_ * D_];
__device__ float g_enh[(long)B_ * L_ * L_];
__device__ float g_att[B_ * L_ * D_];

// ---------------- helpers ----------------------------------------------------
__device__ __forceinline__ uint32_t smem_u32(const void* p) {
    uint32_t a;
    asm("{ .reg .u64 t; cvta.to.shared.u64 t, %1; cvt.u32.u64 %0, t; }"
        : "=r"(a) : "l"(p));
    return a;
}
__device__ __forceinline__ uint32_t f2tf32(float x) {
    uint32_t r;
    asm("cvt.rna.tf32.f32 %0, %1;" : "=r"(r) : "f"(x));
    return r;
}
__device__ __forceinline__ uint4 hi4(float4 a) {
    uint4 h;
    h.x = f2tf32(a.x); h.y = f2tf32(a.y);
    h.z = f2tf32(a.z); h.w = f2tf32(a.w);
    return h;
}
__device__ __forceinline__ void ldsm4(uint32_t* r, uint32_t addr) {
    asm volatile("ldmatrix.sync.aligned.m8n8.x4.shared.b16 {%0,%1,%2,%3}, [%4];"
                 : "=r"(r[0]), "=r"(r[1]), "=r"(r[2]), "=r"(r[3]) : "r"(addr));
}
__device__ __forceinline__ void mma8(float* d, const uint32_t* a, const uint32_t* b) {
    asm volatile(
        "mma.sync.aligned.m16n8k8.row.col.f32.tf32.tf32.f32 "
        "{%0,%1,%2,%3}, {%4,%5,%6,%7}, {%8,%9}, {%0,%1,%2,%3};"
        : "+f"(d[0]), "+f"(d[1]), "+f"(d[2]), "+f"(d[3])
        : "r"(a[0]), "r"(a[1]), "r"(a[2]), "r"(a[3]), "r"(b[0]), "r"(b[1]));
}
__device__ __forceinline__ void mma16(float* d, const uint32_t* a, const uint32_t* b) {
    asm volatile(
        "mma.sync.aligned.m16n8k16.row.col.f32.bf16.bf16.f32 "
        "{%0,%1,%2,%3}, {%4,%5,%6,%7}, {%8,%9}, {%0,%1,%2,%3};"
        : "+f"(d[0]), "+f"(d[1]), "+f"(d[2]), "+f"(d[3])
        : "r"(a[0]), "r"(a[1]), "r"(a[2]), "r"(a[3]), "r"(b[0]), "r"(b[1]));
}
// bf16 2-level split of 4 floats -> hi(4xbf16 as uint2), lo(uint2)
__device__ __forceinline__ void splitbf4(float4 a, uint2& h, uint2& l) {
    float e[4] = {a.x, a.y, a.z, a.w};
    uint16_t hh[4], ll[4];
#pragma unroll
    for (int i = 0; i < 4; i++) {
        __nv_bfloat16 bh = __float2bfloat16_rn(e[i]);
        float hf = __bfloat162float(bh);
        __nv_bfloat16 bl = __float2bfloat16_rn(e[i] - hf);
        hh[i] = *reinterpret_cast<uint16_t*>(&bh);
        ll[i] = *reinterpret_cast<uint16_t*>(&bl);
    }
    h.x = (uint32_t)hh[0] | ((uint32_t)hh[1] << 16);
    h.y = (uint32_t)hh[2] | ((uint32_t)hh[3] << 16);
    l.x = (uint32_t)ll[0] | ((uint32_t)ll[1] << 16);
    l.y = (uint32_t)ll[2] | ((uint32_t)ll[3] << 16);
}

// ---------------------------------------------------------------------------
// bf16x3 GEMM core (hi/lo split; AhBh + AhBl + AlBh). Elementwise err ~2^-16.
// C[m,n] = sum_k A[m,k]*B[n,k] (+bias[n]).
// CTA 128x128, K-chunk 32, 8 warps (2m x 4n), warp tile 64x32, mma.m16n8k16.
// SINGLE smem buffer (40960 B: Ah/Al/Bh/Bl each 128 rows x 80 B) -> 2 CTAs/SM;
// cross-CTA overlap covers the load/MMA sync gaps (R3-validated scheme).
// mma:ldsm = 96:24 = 4:1 per k32 chunk per warp.
// ---------------------------------------------------------------------------
#define BF_AR 10240   // 128*80 bytes per array
#define BF_STG 40960  // 4 arrays

__device__ __forceinline__ void bf_core(
    const float* __restrict__ A, const float* __restrict__ B,
    float* __restrict__ C, const float* __restrict__ bias,
    int N, int K, char* smc)
{
    const uint32_t smb = smem_u32(smc);

    const int tid = threadIdx.x;
    const int lane = tid & 31;
    const int warp = tid >> 5;
    const int wm = warp >> 2;        // 0..1 -> 64-row half
    const int wn = warp & 3;         // 0..3 -> 32-col slice
    const int bm = blockIdx.y * 128;
    const int bn = blockIdx.x * 128;

    const int row0 = tid >> 3;       // 0..31
    const int c4 = (tid & 7) << 2;   // element col 0..28
    const float* Ap = A + (long)(bm + row0) * K + c4;
    const float* Bp = B + (long)(bn + row0) * K + c4;

    // ldmatrix byte offsets (80B rows; 16B k8-halves)
    const uint32_t aOff = (uint32_t)(wm * 64 + (lane & 15)) * 80u + (lane & 16);
    const uint32_t bOff = (uint32_t)(wn * 32 + (lane & 7) + ((lane & 16) >> 1)) * 80u
                          + ((lane & 8) << 1) + 2u * BF_AR;
    const uint32_t R16B = 16 * 80;   // 16-row byte stride

    float acc[4][4][4];
#pragma unroll
    for (int m = 0; m < 4; m++)
#pragma unroll
        for (int n = 0; n < 4; n++)
#pragma unroll
            for (int r = 0; r < 4; r++) acc[m][n][r] = 0.f;

    const int NC = K >> 5;

    for (int c = 0; c < NC; c++) {
        const int k0 = c << 5;
        float4 av[4], bv[4];
#pragma unroll
        for (int it = 0; it < 4; it++) {
            av[it] = *(const float4*)(Ap + (long)(it * 32) * K + k0);
            bv[it] = *(const float4*)(Bp + (long)(it * 32) * K + k0);
        }
        __syncthreads();  // previous chunk's LDSM done
#pragma unroll
        for (int it = 0; it < 4; it++) {
            const int idx = (row0 + it * 32) * 80 + c4 * 2;
            uint2 h, l;
            splitbf4(av[it], h, l);
            *(uint2*)(smc + idx) = h;
            *(uint2*)(smc + BF_AR + idx) = l;
            splitbf4(bv[it], h, l);
            *(uint2*)(smc + 2 * BF_AR + idx) = h;
            *(uint2*)(smc + 3 * BF_AR + idx) = l;
        }
        __syncthreads();

        const uint32_t aH = smb + aOff;
        const uint32_t aL = aH + BF_AR;
        const uint32_t bH = smb + bOff;
        const uint32_t bL = bH + BF_AR;
#pragma unroll
        for (int s = 0; s < 2; s++) {          // two k16 steps per chunk
            const uint32_t ks = (uint32_t)s * 32;  // 16 bf16 = 32 bytes
            uint32_t bh[8], bl[8];
            ldsm4(bh + 0, bH + ks);
            ldsm4(bh + 4, bH + ks + R16B);
            ldsm4(bl + 0, bL + ks);
            ldsm4(bl + 4, bL + ks + R16B);
            uint32_t af[16];
#pragma unroll
            for (int m = 0; m < 4; m++)
                ldsm4(af + 4 * m, aH + ks + (uint32_t)(m * 16 * 80));
#pragma unroll
            for (int m = 0; m < 4; m++)
#pragma unroll
                for (int n = 0; n < 4; n++) {
                    mma16(acc[m][n], af + 4 * m, bh + 2 * n);
                    mma16(acc[m][n], af + 4 * m, bl + 2 * n);
                }
#pragma unroll
            for (int m = 0; m < 4; m++)
                ldsm4(af + 4 * m, aL + ks + (uint32_t)(m * 16 * 80));
#pragma unroll
            for (int m = 0; m < 4; m++)
#pragma unroll
                for (int n = 0; n < 4; n++)
                    mma16(acc[m][n], af + 4 * m, bh + 2 * n);
        }
    }

    const int g = lane >> 2;
    const int t = lane & 3;
#pragma unroll
    for (int n = 0; n < 4; n++) {
        const int col = bn + wn * 32 + n * 8 + t * 2;
        float b0 = 0.f, b1 = 0.f;
        if (bias) { b0 = bias[col]; b1 = bias[col + 1]; }
#pragma unroll
        for (int m = 0; m < 4; m++) {
            const int r0 = bm + wm * 64 + m * 16 + g;
            float2 v0 = make_float2(acc[m][n][0] + b0, acc[m][n][1] + b1);
            float2 v1 = make_float2(acc[m][n][2] + b0, acc[m][n][3] + b1);
            *(float2*)(C + (long)r0 * N + col) = v0;
            *(float2*)(C + (long)(r0 + 8) * N + col) = v1;
        }
    }
}

__global__ void __launch_bounds__(256, 2) tc_gemm_bf(
    const float* __restrict__ A, const float* __restrict__ B,
    float* __restrict__ C, const float* __restrict__ bias,
    int N, int K, long sA, long sB, long sC)
{
    extern __shared__ char smc[];
    bf_core(A + (long)blockIdx.z * sA, B + (long)blockIdx.z * sB,
            C + (long)blockIdx.z * sC, bias, N, K, smc);
}

// Merged projections (all bf16x3): z selects (input, W, bias, output).
struct ProjArgs {
    const float* in[4];
    const float* W[4];
    const float* bias[4];
    float* out[4];
};

__global__ void __launch_bounds__(256, 2) tc_proj(ProjArgs p)
{
    extern __shared__ char smc[];
    const int z = blockIdx.z;
    bf_core(p.in[z], p.W[z], p.out[z], p.bias[z], D_, D_, smc);
}

// ---------------------------------------------------------------------------
// Batched transpose: in [B][L][D] -> out [B][D][L]
// ---------------------------------------------------------------------------
__global__ void transpose_ld(const float* __restrict__ in, float* __restrict__ out)
{
    __shared__ float t[32][33];
    const int b = blockIdx.z;
    const int d0 = blockIdx.x * 32;
    const int l0 = blockIdx.y * 32;
    const int x = threadIdx.x;
    const int y = threadIdx.y;
    const float* ib = in + ((long)b * L_ + l0) * D_ + d0;
#pragma unroll
    for (int i = y; i < 32; i += 8) t[i][x] = ib[(long)i * D_ + x];
    __syncthreads();
    float* ob = out + ((long)b * D_ + d0) * L_ + l0;
#pragma unroll
    for (int i = y; i < 32; i += 8) ob[(long)i * L_ + x] = t[x][i];
}

// ---------------------------------------------------------------------------
// Fused attention via mma.sync (validated R6/R8/R9/R10).
//   S = QK^T (1x tf32) ; S = (S+E)/16 ; online softmax ; O = P V (1x tf32).
// ---------------------------------------------------------------------------
__global__ void __launch_bounds__(256, 2) attn_mma(
    const float* __restrict__ Q, const float* __restrict__ K,
    const float* __restrict__ V, const float* __restrict__ E,
    float* __restrict__ O)
{
    extern __shared__ float sh[];
    float* sQ = sh;                    // 128*68
    float* sK = sh + 128 * 68;         // 64*68
    float* sVh = sK + 64 * 68;         // [d][key]

    const int b = blockIdx.y / H_;
    const int h = blockIdx.y % H_;
    const int l0 = blockIdx.x * 128;
    const int tid = threadIdx.x;
    const int lane = tid & 31;
    const int w = tid >> 5;
    const int g = lane >> 2;
    const int t = lane & 3;

    const float* qb = Q + ((long)b * L_ + l0) * D_ + h * 64;
    const float* kb = K + (long)b * L_ * D_ + h * 64;
    const float* vb = V + (long)b * L_ * D_ + h * 64;
    const float* e0 = E + ((long)b * L_ + l0 + w * 16 + g) * L_;
    const float* e1 = e0 + 8 * L_;

#pragma unroll
    for (int it = 0; it < 8; it++) {
        int f = tid + it * 256;
        int row = f >> 4;
        int d4 = (f & 15) << 2;
        float4 v = *(const float4*)(qb + (long)row * D_ + d4);
        *(uint4*)(sQ + row * 68 + d4) = hi4(v);
    }

    const uint32_t sQa = smem_u32(sQ) +
        ((((uint32_t)(w * 16 + (lane & 15)) * 68u) + ((lane & 16) >> 2)) << 2);
    const uint32_t bPat =
        ((((uint32_t)((lane & 7) + ((lane & 16) >> 1)) * 68u) +
          ((lane & 8) >> 1)) << 2);
    const uint32_t sKa = smem_u32(sK) + bPat;
    const uint32_t sVha = smem_u32(sVh) + bPat;
    const uint32_t R16 = (16 * 68) << 2;

    float o[8][4];
#pragma unroll
    for (int j = 0; j < 8; j++)
#pragma unroll
        for (int r = 0; r < 4; r++) o[j][r] = 0.f;
    float m0 = -1e30f, m1 = -1e30f, sum0 = 0.f, sum1 = 0.f;

    for (int jb = 0; jb < 16; jb++) {
        __syncthreads();
#pragma unroll
        for (int it = 0; it < 4; it++) {
            int f = tid + it * 256;
            int key = f >> 4;
            int d4 = (f & 15) << 2;
            float4 v = *(const float4*)(kb + (long)(jb * 64 + key) * D_ + d4);
            *(uint4*)(sK + key * 68 + d4) = hi4(v);
        }
#pragma unroll
        for (int it = 0; it < 4; it++) {
            int f = tid + it * 256;
            int key = f >> 4;
            int d4 = (f & 15) << 2;
            float4 v = *(const float4*)(vb + (long)(jb * 64 + key) * D_ + d4);
            float vv[4] = {v.x, v.y, v.z, v.w};
#pragma unroll
            for (int i = 0; i < 4; i++)
                *(uint32_t*)(sVh + (d4 + i) * 68 + key) = f2tf32(vv[i]);
        }
        __syncthreads();

        float accS[8][4];
#pragma unroll
        for (int j = 0; j < 8; j++)
#pragma unroll
            for (int r = 0; r < 4; r++) accS[j][r] = 0.f;
#pragma unroll
        for (int s = 0; s < 8; s++) {
            const uint32_t ks = (uint32_t)s * 32;
            uint32_t af[4], bf[16];
            ldsm4(af, sQa + ks);
            ldsm4(bf + 0,  sKa + ks);
            ldsm4(bf + 4,  sKa + ks + R16);
            ldsm4(bf + 8,  sKa + ks + 2 * R16);
            ldsm4(bf + 12, sKa + ks + 3 * R16);
#pragma unroll
            for (int j = 0; j < 8; j++) mma8(accS[j], af, bf + 2 * j);
        }

#pragma unroll
        for (int j = 0; j < 8; j++) {
            const int col = jb * 64 + 8 * j + 2 * t;
            float2 ea = *(const float2*)(e0 + col);
            float2 ebv = *(const float2*)(e1 + col);
            accS[j][0] = (accS[j][0] + ea.x) * 0.0625f;
            accS[j][1] = (accS[j][1] + ea.y) * 0.0625f;
            accS[j][2] = (accS[j][2] + ebv.x) * 0.0625f;
            accS[j][3] = (accS[j][3] + ebv.y) * 0.0625f;
        }

        float mx0 = -1e30f, mx1 = -1e30f;
#pragma unroll
        for (int j = 0; j < 8; j++) {
            mx0 = fmaxf(mx0, fmaxf(accS[j][0], accS[j][1]));
            mx1 = fmaxf(mx1, fmaxf(accS[j][2], accS[j][3]));
        }
#pragma unroll
        for (int off = 1; off <= 2; off <<= 1) {
            mx0 = fmaxf(mx0, __shfl_xor_sync(0xffffffffu, mx0, off));
            mx1 = fmaxf(mx1, __shfl_xor_sync(0xffffffffu, mx1, off));
        }
        const float nm0 = fmaxf(m0, mx0), nm1 = fmaxf(m1, mx1);
        const float sc0 = __expf(m0 - nm0), sc1 = __expf(m1 - nm1);
        float rs0 = 0.f, rs1 = 0.f;
#pragma unroll
        for (int j = 0; j < 8; j++) {
            accS[j][0] = __expf(accS[j][0] - nm0);
            accS[j][1] = __expf(accS[j][1] - nm0);
            accS[j][2] = __expf(accS[j][2] - nm1);
            accS[j][3] = __expf(accS[j][3] - nm1);
            rs0 += accS[j][0] + accS[j][1];
            rs1 += accS[j][2] + accS[j][3];
        }
#pragma unroll
        for (int off = 1; off <= 2; off <<= 1) {
            rs0 += __shfl_xor_sync(0xffffffffu, rs0, off);
            rs1 += __shfl_xor_sync(0xffffffffu, rs1, off);
        }
        sum0 = sum0 * sc0 + rs0;
        sum1 = sum1 * sc1 + rs1;
        m0 = nm0; m1 = nm1;
#pragma unroll
        for (int j = 0; j < 8; j++) {
            o[j][0] *= sc0; o[j][1] *= sc0;
            o[j][2] *= sc1; o[j][3] *= sc1;
        }

        const int sl0 = (lane & ~3) | (t >> 1);
        const int sl2 = sl0 + 2;
#pragma unroll
        for (int kt = 0; kt < 8; kt++) {
            float p00 = __shfl_sync(0xffffffffu, accS[kt][0], sl0);
            float p01 = __shfl_sync(0xffffffffu, accS[kt][1], sl0);
            float p20 = __shfl_sync(0xffffffffu, accS[kt][0], sl2);
            float p21 = __shfl_sync(0xffffffffu, accS[kt][1], sl2);
            float p10 = __shfl_sync(0xffffffffu, accS[kt][2], sl0);
            float p11 = __shfl_sync(0xffffffffu, accS[kt][3], sl0);
            float p30 = __shfl_sync(0xffffffffu, accS[kt][2], sl2);
            float p31 = __shfl_sync(0xffffffffu, accS[kt][3], sl2);
            float a0 = (t & 1) ? p01 : p00;
            float a1 = (t & 1) ? p11 : p10;
            float a2 = (t & 1) ? p21 : p20;
            float a3 = (t & 1) ? p31 : p30;
            uint32_t ah[4];
            ah[0] = f2tf32(a0); ah[1] = f2tf32(a1);
            ah[2] = f2tf32(a2); ah[3] = f2tf32(a3);

            const uint32_t ks = (uint32_t)kt * 32;
            uint32_t bvr[16];
            ldsm4(bvr + 0,  sVha + ks);
            ldsm4(bvr + 4,  sVha + ks + R16);
            ldsm4(bvr + 8,  sVha + ks + 2 * R16);
            ldsm4(bvr + 12, sVha + ks + 3 * R16);
#pragma unroll
            for (int j = 0; j < 8; j++)
                mma8(o[j], ah, bvr + 2 * j);
        }
    }

    const float inv0 = 1.f / sum0, inv1 = 1.f / sum1;
    float* ob = O + ((long)b * L_ + l0 + w * 16) * D_ + h * 64;
#pragma unroll
    for (int j = 0; j < 8; j++) {
        const int col = 8 * j + 2 * t;
        *(float2*)(ob + (long)g * D_ + col) =
            make_float2(o[j][0] * inv0, o[j][1] * inv0);
        *(float2*)(ob + (long)(g + 8) * D_ + col) =
            make_float2(o[j][2] * inv1, o[j][3] * inv1);
    }
}

// ---------------------------------------------------------------------------
extern "C" void kernel_launch(void* const* d_in, const int* in_sizes, int n_in,
                              void* d_out, int out_size)
{
    const float* query = (const float*)d_in[0];
    const float* key   = (const float*)d_in[1];
    const float* value = (const float*)d_in[2];
    const float* news  = (const float*)d_in[3];
    const float* Wq = (const float*)d_in[4];
    const float* bq = (const float*)d_in[5];
    const float* Wk = (const float*)d_in[6];
    const float* bk = (const float*)d_in[7];
    const float* Wv = (const float*)d_in[8];
    const float* bv = (const float*)d_in[9];
    const float* Wn = (const float*)d_in[10];
    const float* bn = (const float*)d_in[11];
    const float* Wo = (const float*)d_in[12];
    const float* bo = (const float*)d_in[13];
    // d_in[14] = pos. Mathematically irrelevant (swapaxes of swapped enh == enh).

    float *pq, *pk, *pv, *pn, *pnkT, *pG, *pT, *penh, *patt;
    cudaGetSymbolAddress((void**)&pq,   g_q);
    cudaGetSymbolAddress((void**)&pk,   g_k);
    cudaGetSymbolAddress((void**)&pv,   g_v);
    cudaGetSymbolAddress((void**)&pn,   g_n);
    cudaGetSymbolAddress((void**)&pnkT, g_nkT);
    cudaGetSymbolAddress((void**)&pG,   g_G);
    cudaGetSymbolAddress((void**)&pT,   g_T);
    cudaGetSymbolAddress((void**)&penh, g_enh);
    cudaGetSymbolAddress((void**)&patt, g_att);

    const int M = B_ * L_;  // 8192
    dim3 blk(256);
    const int smemBF = BF_STG;  // 40960 (single buffer)
    cudaFuncSetAttribute(tc_proj,    cudaFuncAttributeMaxDynamicSharedMemorySize, smemBF);
    cudaFuncSetAttribute(tc_gemm_bf, cudaFuncAttributeMaxDynamicSharedMemorySize, smemBF);

    // all 4 projections in one launch (all bf16x3)
    ProjArgs pa;
    pa.in[0] = query; pa.in[1] = key; pa.in[2] = news; pa.in[3] = value;
    pa.W[0] = Wq; pa.W[1] = Wk; pa.W[2] = Wn; pa.W[3] = Wv;
    pa.bias[0] = bq; pa.bias[1] = bk; pa.bias[2] = bn; pa.bias[3] = bv;
    pa.out[0] = pq; pa.out[1] = pk; pa.out[2] = pn; pa.out[3] = pv;
    tc_proj<<<dim3(D_ / 128, M / 128, 4), blk, smemBF>>>(pa);

    // enh = q (nk^T nk) k^T (bf16x3 chain)
    transpose_ld<<<dim3(D_ / 32, L_ / 32, B_), dim3(32, 8)>>>(pn, pnkT);
    tc_gemm_bf<<<dim3(D_ / 128, D_ / 128, B_), blk, smemBF>>>(pnkT, pnkT, pG, nullptr,
        D_, L_, (long)D_ * L_, (long)D_ * L_, (long)D_ * D_);
    tc_gemm_bf<<<dim3(D_ / 128, L_ / 128, B_), blk, smemBF>>>(pq, pG, pT, nullptr,
        D_, D_, (long)L_ * D_, (long)D_ * D_, (long)L_ * D_);
    tc_gemm_bf<<<dim3(L_ / 128, L_ / 128, B_), blk, smemBF>>>(pT, pk, penh, nullptr,
        L_, D_, (long)L_ * D_, (long)L_ * D_, (long)L_ * L_);

    // fused attention
    const int attn_smem = (128 * 68 + 2 * 64 * 68) * 4;  // 69632
    cudaFuncSetAttribute(attn_mma, cudaFuncAttributeMaxDynamicSharedMemorySize,
                         attn_smem);
    attn_mma<<<dim3(L_ / 128, B_ * H_), blk, attn_smem>>>(pq, pk, pv, penh, patt);

    // output projection (bf16x3) -> d_out
    tc_gemm_bf<<<dim3(D_ / 128, M / 128, 1), blk, smemBF>>>(patt, Wo, (float*)d_out, bo,
                                                            D_, D_, 0, 0, 0);
}